// round 10
// baseline (speedup 1.0000x reference)
#include <cuda_runtime.h>
#include <math.h>

// R10 = R9 resubmission (R9 died to infra "container failed twice" before
// executing; kernel logic audited, no defect found).

#define B_   32
#define S_   200
#define H_   512
#define G4   2048
#define ED_  256
#define NF_  19
#define IN0  275
#define M_   6400
#define PD_  531
#define NCTA 128
#define TW   132                      // smem tile row stride (floats)

// ---------------- scratch (static device memory; no allocation) ----------------
__device__ float g_inpT[IN0 * M_];     // LSTM-0 input, k-major [IN0][M]
__device__ float g_X[M_ * G4];         // input-gate GEMM result (row-major [M][4H])
__device__ float g_hall0T[H_ * M_];    // layer-0 hidden, k-major [H][M]
__device__ float g_hall1T[H_ * M_];    // layer-1 hidden, k-major [H][M]
__device__ float g_WT[512 * G4];       // transposed W_ih (reused L0/L1)
__device__ float g_hbufA[H_ * B_];     // h ping  ([H][B])
__device__ float g_hbufB[H_ * B_];     // h pong  ([H][B])
__device__ float g_cst[H_ * B_];       // c init  ([H][B])
__device__ float2 g_partial[32];       // per-block (bce_sum, mask_sum)
__device__ unsigned int g_bar_count = 0;
__device__ volatile unsigned int g_bar_gen = 0;

// ---------------- packed fp32x2 helpers (Blackwell) ----------------------------
__device__ __forceinline__ unsigned long long pk2(float lo, float hi) {
    unsigned long long r;
    asm("mov.b64 %0,{%1,%2};" : "=l"(r) : "f"(lo), "f"(hi));
    return r;
}
__device__ __forceinline__ void ffma2(unsigned long long& d,
                                      unsigned long long a, unsigned long long b) {
    asm("fma.rn.f32x2 %0,%1,%2,%0;" : "+l"(d) : "l"(a), "l"(b));
}
__device__ __forceinline__ float2 up2(unsigned long long v) {
    float2 f;
    asm("mov.b64 {%0,%1},%2;" : "=f"(f.x), "=f"(f.y) : "l"(v));
    return f;
}
__device__ __forceinline__ void cp16(void* sdst, const void* gsrc) {
    unsigned s = (unsigned)__cvta_generic_to_shared(sdst);
    asm volatile("cp.async.cg.shared.global [%0],[%1],16;" :: "r"(s), "l"(gsrc));
}

// ---------------- grid-wide barrier (atomic + generation; known-good) -----------
__device__ __forceinline__ void grid_barrier(int nblocks) {
    __syncthreads();
    if (threadIdx.x == 0) {
        unsigned int gen = g_bar_gen;
        __threadfence();
        if (atomicAdd(&g_bar_count, 1u) == (unsigned)(nblocks - 1)) {
            g_bar_count = 0;
            __threadfence();
            g_bar_gen = gen + 1;
        } else {
            while (g_bar_gen == gen) { __nanosleep(32); }
        }
        __threadfence();
    }
    __syncthreads();
}

// ---------------- build LSTM-0 input (k-major transposed) -----------------------
__global__ void build_inp_kernel(const int* __restrict__ xd,
                                 const float* __restrict__ emb,
                                 const float* __restrict__ Cm,
                                 const float* __restrict__ rep,
                                 const float* __restrict__ seq,
                                 const float* __restrict__ past,
                                 float* __restrict__ inpT) {
    int idx = blockIdx.x * 256 + threadIdx.x;
    if (idx >= M_ * IN0) return;
    int d = idx / M_, col = idx - d * M_;
    int t = col >> 5, b = col & 31;
    float v;
    if (d < ED_) {
        int x = xd[b * S_ + t];
        v = emb[(size_t)x * ED_ + d];
    } else {
        int f = d - ED_;
        float cv;
        if (f < 7)       cv = rep[(b * (S_ + 1) + t) * 7 + f];
        else if (f < 13) cv = seq[(b * (S_ + 1) + t) * 6 + (f - 7)];
        else             cv = past[(b * (S_ + 1) + t) * 6 + (f - 13)];
        v = Cm[(b * S_ + t) * NF_ + f] * cv;
    }
    inpT[idx] = v;
}

// ---------------- generic tiled transpose: out[C][R] = in[R][C]^T ---------------
__global__ void transpose_kernel(const float* __restrict__ in,
                                 float* __restrict__ out, int R, int C) {
    __shared__ float tile[32][33];
    int c0 = blockIdx.x * 32, r0 = blockIdx.y * 32;
    int x = c0 + threadIdx.x;
#pragma unroll
    for (int j = 0; j < 32; j += 8) {
        int y = r0 + threadIdx.y + j;
        if (y < R && x < C) tile[threadIdx.y + j][threadIdx.x] = in[(size_t)y * C + x];
    }
    __syncthreads();
    int x2 = r0 + threadIdx.x;
#pragma unroll
    for (int j = 0; j < 32; j += 8) {
        int y2 = c0 + threadIdx.y + j;
        if (y2 < C && x2 < R) out[(size_t)y2 * R + x2] = tile[threadIdx.x][threadIdx.y + j];
    }
}

// ---------------- init states into [H][B] ---------------------------------------
__global__ void init_state_kernel(const float* __restrict__ ih,
                                  const float* __restrict__ ic, int layer,
                                  float* __restrict__ hbuf0, float* __restrict__ cst) {
    int idx = blockIdx.x * 256 + threadIdx.x;
    if (idx >= H_ * B_) return;
    int j = idx >> 5, b = idx & 31;
    hbuf0[j * B_ + b] = ih[layer * B_ * H_ + b * H_ + j];
    cst[j * B_ + b]   = ic[layer * B_ * H_ + b * H_ + j];
}

// ---------------- GEMM (k-major inputs): C[M][N] = AT^T * BT + bias1 + bias2 ----
// AT: [K][M], BT: [K][N]. 128x128 tile, BK=32, 256 threads, cp.async 3-stage.
__device__ __forceinline__ void gemm_load_stage(
    float* Abuf, float* Bbuf, const float* AT, const float* BT,
    int s, int m0, int n0, int M, int N, int K, int tid) {
    int off = (s % 3) * 32 * TW;
    int kk = s * 32;
#pragma unroll
    for (int i = 0; i < 4; i++) {
        int task = tid + i * 256;
        int row = task >> 5, c = task & 31;
        float* ad = &Abuf[off + row * TW + c * 4];
        float* bd = &Bbuf[off + row * TW + c * 4];
        if (kk + row < K) {
            cp16(ad, AT + (size_t)(kk + row) * M + m0 + c * 4);
            cp16(bd, BT + (size_t)(kk + row) * N + n0 + c * 4);
        } else {
            *(float4*)ad = make_float4(0.f, 0.f, 0.f, 0.f);
            *(float4*)bd = make_float4(0.f, 0.f, 0.f, 0.f);
        }
    }
    asm volatile("cp.async.commit_group;" ::);
}

__global__ void __launch_bounds__(256) gemm_tt_bias(
    const float* __restrict__ AT, const float* __restrict__ BT,
    const float* __restrict__ bias1, const float* __restrict__ bias2,
    float* __restrict__ Cmat, int M, int N, int K) {
    extern __shared__ float sm[];
    float* Abuf = sm;
    float* Bbuf = sm + 3 * 32 * TW;
    int m0 = blockIdx.y * 128, n0 = blockIdx.x * 128;
    int tid = threadIdx.x;
    int ty = tid >> 4, tx = tid & 15;
    int nk = (K + 31) / 32;

    unsigned long long acc[8][4];
#pragma unroll
    for (int i = 0; i < 8; i++)
#pragma unroll
        for (int j = 0; j < 4; j++) acc[i][j] = 0ull;

    gemm_load_stage(Abuf, Bbuf, AT, BT, 0, m0, n0, M, N, K, tid);
    if (nk > 1) gemm_load_stage(Abuf, Bbuf, AT, BT, 1, m0, n0, M, N, K, tid);

    for (int s = 0; s < nk; s++) {
        if (s + 2 < nk) {
            gemm_load_stage(Abuf, Bbuf, AT, BT, s + 2, m0, n0, M, N, K, tid);
            asm volatile("cp.async.wait_group 2;" ::);
        } else if (s + 1 < nk) {
            asm volatile("cp.async.wait_group 1;" ::);
        } else {
            asm volatile("cp.async.wait_group 0;" ::);
        }
        __syncthreads();
        const float* As = Abuf + (s % 3) * 32 * TW;
        const float* Bs = Bbuf + (s % 3) * 32 * TW;
#pragma unroll 8
        for (int k = 0; k < 32; k++) {
            float4 a0 = *(const float4*)&As[k * TW + ty * 8];
            float4 a1 = *(const float4*)&As[k * TW + ty * 8 + 4];
            ulonglong2 b0 = *(const ulonglong2*)&Bs[k * TW + tx * 8];
            ulonglong2 b1 = *(const ulonglong2*)&Bs[k * TW + tx * 8 + 4];
            unsigned long long aa[8];
            aa[0] = pk2(a0.x, a0.x); aa[1] = pk2(a0.y, a0.y);
            aa[2] = pk2(a0.z, a0.z); aa[3] = pk2(a0.w, a0.w);
            aa[4] = pk2(a1.x, a1.x); aa[5] = pk2(a1.y, a1.y);
            aa[6] = pk2(a1.z, a1.z); aa[7] = pk2(a1.w, a1.w);
#pragma unroll
            for (int i = 0; i < 8; i++) {
                ffma2(acc[i][0], aa[i], b0.x);
                ffma2(acc[i][1], aa[i], b0.y);
                ffma2(acc[i][2], aa[i], b1.x);
                ffma2(acc[i][3], aa[i], b1.y);
            }
        }
        __syncthreads();
    }
#pragma unroll
    for (int i = 0; i < 8; i++) {
        int m = m0 + ty * 8 + i;
#pragma unroll
        for (int j = 0; j < 4; j++) {
            int n = n0 + tx * 8 + j * 2;
            float2 v = up2(acc[i][j]);
            Cmat[(size_t)m * N + n]     = v.x + bias1[n]     + bias2[n];
            Cmat[(size_t)m * N + n + 1] = v.y + bias1[n + 1] + bias2[n + 1];
        }
    }
}
#define GSMEM (6 * 32 * TW * (int)sizeof(float))

// ---------------- persistent LSTM layer scan ------------------------------------
// 128 CTAs x 512 threads (16 warps, 4/SMSP for latency hiding).
// CTA owns 4 hidden units (16 gate rows in smem); each warp owns a UNIQUE
// 32-element k-slice (h read exactly once per CTA -> L2 traffic unchanged).
__global__ void __launch_bounds__(512, 1) lstm_layer_kernel(
    const float* __restrict__ X,     // [S*B][4H], row = t*B+b (bias folded in)
    const float* __restrict__ Whh,   // [4H][H]
    float* __restrict__ hbuf0,       // [H][B] ping (init h)
    float* __restrict__ hbuf1,       // [H][B] pong
    const float* __restrict__ cst,   // [H][B] init c
    float* __restrict__ hallT)       // [H][S*B] out (k-major)
{
    extern __shared__ float smem[];
    float* Ws   = smem;               // [16][512]   32 KB
    float* psum = smem + 16 * 512;    // [16][16][32] 32 KB

    int tid = threadIdx.x;
    int jb = blockIdx.x * 4;
    int warp = tid >> 5, lane = tid & 31;

    for (int idx = tid; idx < 16 * 512; idx += 512) {
        int r = idx >> 9, k = idx & 511;
        int gr = (r >> 2) * H_ + jb + (r & 3);
        Ws[r * 512 + k] = Whh[(size_t)gr * H_ + k];
    }
    int u = warp, b = lane;                 // epilogue mapping (tid<128)
    float cc = 0.f;
    if (tid < 128) cc = cst[(jb + u) * B_ + b];
    __syncthreads();

    const int k0 = warp * 32;               // unique 32-k slice per warp
    for (int t = 0; t < S_; t++) {
        const float* hprev = (t & 1) ? hbuf1 : hbuf0;
        float* hnext       = (t & 1) ? hbuf0 : hbuf1;

        float xi = 0.f, xf = 0.f, xg = 0.f, xo = 0.f;
        if (tid < 128) {
            const float* xrow = X + (size_t)(t * B_ + b) * G4 + jb + u;
            xi = xrow[0]; xf = xrow[512]; xg = xrow[1024]; xo = xrow[1536];
        }

        unsigned long long acc[16];
#pragma unroll
        for (int r = 0; r < 16; r++) acc[r] = 0ull;
        const float* hp = hprev + k0 * B_ + lane;
#pragma unroll
        for (int kb = 0; kb < 4; kb++) {
            float h0 = __ldcg(hp + (kb * 8 + 0) * B_);
            float h1 = __ldcg(hp + (kb * 8 + 1) * B_);
            float h2 = __ldcg(hp + (kb * 8 + 2) * B_);
            float h3 = __ldcg(hp + (kb * 8 + 3) * B_);
            float h4 = __ldcg(hp + (kb * 8 + 4) * B_);
            float h5 = __ldcg(hp + (kb * 8 + 5) * B_);
            float h6 = __ldcg(hp + (kb * 8 + 6) * B_);
            float h7 = __ldcg(hp + (kb * 8 + 7) * B_);
            unsigned long long hv0 = pk2(h0, h1), hv1 = pk2(h2, h3);
            unsigned long long hv2 = pk2(h4, h5), hv3 = pk2(h6, h7);
            const float* wb = Ws + k0 + kb * 8;
#pragma unroll
            for (int r = 0; r < 16; r++) {
                ulonglong2 w0 = *(const ulonglong2*)(wb + r * 512);
                ulonglong2 w1 = *(const ulonglong2*)(wb + r * 512 + 4);
                ffma2(acc[r], hv0, w0.x);
                ffma2(acc[r], hv1, w0.y);
                ffma2(acc[r], hv2, w1.x);
                ffma2(acc[r], hv3, w1.y);
            }
        }
#pragma unroll
        for (int r = 0; r < 16; r++) {
            float2 p = up2(acc[r]);
            psum[(warp * 16 + r) * 32 + lane] = p.x + p.y;
        }
        __syncthreads();

        if (tid < 128) {
            float s_i = xi, s_f = xf, s_g = xg, s_o = xo;
#pragma unroll
            for (int w = 0; w < 16; w++) {
                s_i += psum[(w * 16 + 0  + u) * 32 + b];
                s_f += psum[(w * 16 + 4  + u) * 32 + b];
                s_g += psum[(w * 16 + 8  + u) * 32 + b];
                s_o += psum[(w * 16 + 12 + u) * 32 + b];
            }
            float ig = 1.f / (1.f + expf(-s_i));
            float fg = 1.f / (1.f + expf(-s_f));
            float og = 1.f / (1.f + expf(-s_o));
            cc = fg * cc + ig * tanhf(s_g);
            float hv = og * tanhf(cc);
            __stcg(&hnext[(jb + u) * B_ + b], hv);
            hallT[(size_t)(jb + u) * M_ + t * B_ + b] = hv;
        }
        if (t < S_ - 1) grid_barrier(NCTA);   // kernel boundary syncs final step
    }
}
#define LSMEM ((16 * 512 + 16 * 16 * 32) * (int)sizeof(float))

// ---------------- gathered prediction + BCE partials ----------------------------
__global__ void pred_kernel(const float* __restrict__ hallT,
                            const float* __restrict__ Wp,
                            const float* __restrict__ bp,
                            const int* __restrict__ qt,
                            const float* __restrict__ target,
                            const float* __restrict__ Cm,
                            const float* __restrict__ rep,
                            const float* __restrict__ seq,
                            const float* __restrict__ past,
                            float* __restrict__ out,
                            float2* __restrict__ partial) {
    int col = blockIdx.x * 256 + threadIdx.x;     // t*B+b ordering
    int b = col & 31, s = col >> 5;
    int r = b * S_ + s;
    int q = qt[r];
    const float* wrow = Wp + (size_t)q * PD_;
    const float* hc = hallT + col;
    float acc = bp[q];
#pragma unroll 8
    for (int d = 0; d < H_; d++) acc = fmaf(hc[(size_t)d * M_], wrow[d], acc);
#pragma unroll
    for (int f = 0; f < NF_; f++) {
        float cv;
        if (f < 7)       cv = rep[(b * (S_ + 1) + s + 1) * 7 + f];
        else if (f < 13) cv = seq[(b * (S_ + 1) + s + 1) * 6 + (f - 7)];
        else             cv = past[(b * (S_ + 1) + s + 1) * 6 + (f - 13)];
        float pi = Cm[(b * S_ + s) * NF_ + f] * cv;
        acc = fmaf(pi, wrow[H_ + f], acc);
    }
    float m = (q > 0) ? 1.f : 0.f;
    float tt = target[r];
    float sg = 1.f / (1.f + expf(-acc));
    out[1 + r] = sg * m;
    out[1 + M_ + r] = tt * m;
    float l = fmaxf(acc, 0.f) - acc * tt + log1pf(expf(-fabsf(acc)));

    __shared__ float sb[256], sm2[256];
    sb[threadIdx.x] = l * m;
    sm2[threadIdx.x] = m;
    __syncthreads();
    for (int st = 128; st > 0; st >>= 1) {
        if (threadIdx.x < st) {
            sb[threadIdx.x] += sb[threadIdx.x + st];
            sm2[threadIdx.x] += sm2[threadIdx.x + st];
        }
        __syncthreads();
    }
    if (threadIdx.x == 0) partial[blockIdx.x] = make_float2(sb[0], sm2[0]);
}

__global__ void finalize_kernel(const float2* __restrict__ partial, int n,
                                float* __restrict__ out) {
    __shared__ float sa[32], sc[32];
    float a = 0.f, c = 0.f;
    if (threadIdx.x < n) { float2 p = partial[threadIdx.x]; a = p.x; c = p.y; }
    sa[threadIdx.x] = a; sc[threadIdx.x] = c;
    __syncthreads();
    for (int s = 16; s > 0; s >>= 1) {
        if (threadIdx.x < s) {
            sa[threadIdx.x] += sa[threadIdx.x + s];
            sc[threadIdx.x] += sc[threadIdx.x + s];
        }
        __syncthreads();
    }
    if (threadIdx.x == 0) out[0] = sa[0] / sc[0];
}

// ---------------- launch --------------------------------------------------------
extern "C" void kernel_launch(void* const* d_in, const int* in_sizes, int n_in,
                              void* d_out, int out_size) {
    const int*   x_data = (const int*)d_in[0];
    const int*   q_t    = (const int*)d_in[1];
    const float* target = (const float*)d_in[2];
    const float* rep    = (const float*)d_in[3];
    const float* past   = (const float*)d_in[4];
    const float* seq    = (const float*)d_in[5];
    const float* embed  = (const float*)d_in[6];
    const float* W_ih0  = (const float*)d_in[7];
    const float* W_hh0  = (const float*)d_in[8];
    const float* b_ih0  = (const float*)d_in[9];
    const float* b_hh0  = (const float*)d_in[10];
    const float* W_ih1  = (const float*)d_in[11];
    const float* W_hh1  = (const float*)d_in[12];
    const float* b_ih1  = (const float*)d_in[13];
    const float* b_hh1  = (const float*)d_in[14];
    const float* W_pred = (const float*)d_in[15];
    const float* b_pred = (const float*)d_in[16];
    const float* Cm     = (const float*)d_in[17];
    const float* init_h = (const float*)d_in[18];
    const float* init_c = (const float*)d_in[19];
    float* out = (float*)d_out;

    float *p_inpT, *p_X, *p_h0T, *p_h1T, *p_WT, *p_hA, *p_hB, *p_cst;
    float2* p_part;
    cudaGetSymbolAddress((void**)&p_inpT, g_inpT);
    cudaGetSymbolAddress((void**)&p_X,    g_X);
    cudaGetSymbolAddress((void**)&p_h0T,  g_hall0T);
    cudaGetSymbolAddress((void**)&p_h1T,  g_hall1T);
    cudaGetSymbolAddress((void**)&p_WT,   g_WT);
    cudaGetSymbolAddress((void**)&p_hA,   g_hbufA);
    cudaGetSymbolAddress((void**)&p_hB,   g_hbufB);
    cudaGetSymbolAddress((void**)&p_cst,  g_cst);
    cudaGetSymbolAddress((void**)&p_part, g_partial);

    cudaFuncSetAttribute(gemm_tt_bias,
                         cudaFuncAttributeMaxDynamicSharedMemorySize, GSMEM);
    cudaFuncSetAttribute(lstm_layer_kernel,
                         cudaFuncAttributeMaxDynamicSharedMemorySize, LSMEM);

    // 1) build LSTM-0 input rows (k-major)
    build_inp_kernel<<<(M_ * IN0 + 255) / 256, 256>>>(x_data, embed, Cm, rep, seq,
                                                      past, p_inpT);
    // 2) X0 = inp @ W_ih0^T + b_ih0 + b_hh0   (both operands k-major)
    transpose_kernel<<<dim3((IN0 + 31) / 32, G4 / 32), dim3(32, 8)>>>(W_ih0, p_WT,
                                                                      G4, IN0);
    gemm_tt_bias<<<dim3(G4 / 128, M_ / 128), 256, GSMEM>>>(p_inpT, p_WT, b_ih0,
                                                           b_hh0, p_X, M_, G4, IN0);
    // 3) layer-0 scan
    init_state_kernel<<<(H_ * B_ + 255) / 256, 256>>>(init_h, init_c, 0, p_hA, p_cst);
    lstm_layer_kernel<<<NCTA, 512, LSMEM>>>(p_X, W_hh0, p_hA, p_hB, p_cst, p_h0T);
    // 4) X1 = h1 @ W_ih1^T + b_ih1 + b_hh1
    transpose_kernel<<<dim3(H_ / 32, G4 / 32), dim3(32, 8)>>>(W_ih1, p_WT, G4, H_);
    gemm_tt_bias<<<dim3(G4 / 128, M_ / 128), 256, GSMEM>>>(p_h0T, p_WT, b_ih1,
                                                           b_hh1, p_X, M_, G4, H_);
    // 5) layer-1 scan
    init_state_kernel<<<(H_ * B_ + 255) / 256, 256>>>(init_h, init_c, 1, p_hA, p_cst);
    lstm_layer_kernel<<<NCTA, 512, LSMEM>>>(p_X, W_hh1, p_hA, p_hB, p_cst, p_h1T);
    // 6) gathered prediction head + BCE partials
    pred_kernel<<<M_ / 256, 256>>>(p_h1T, W_pred, b_pred, q_t, target, Cm, rep,
                                   seq, past, out, p_part);
    // 7) loss
    finalize_kernel<<<1, 32>>>(p_part, M_ / 256, out);
}

// round 11
// speedup vs baseline: 1.7578x; 1.7578x over previous
#include <cuda_runtime.h>
#include <math.h>

// R11: fused 2-layer pipelined scan (201 steps, L1 lags L0 by one step).
// Step engine (256 thr, atomic barrier, interleaved __ldcg) = R8 known-good.

#define B_   32
#define S_   200
#define H_   512
#define G4   2048
#define ED_  256
#define NF_  19
#define IN0  275
#define M_   6400
#define PD_  531
#define NCTA 128
#define TW   132                      // smem tile row stride (floats)

// ---------------- scratch (static device memory; no allocation) ----------------
__device__ float g_inpT[IN0 * M_];     // LSTM-0 input, k-major [IN0][M]
__device__ float g_X[M_ * G4];         // X0 = inp@Wih0^T + biases (row-major)
__device__ float g_hall1T[H_ * M_];    // layer-1 hidden, k-major [H][M]
__device__ float g_WT[512 * G4];       // transposed W_ih0
__device__ float g_h0A[H_ * B_];       // h0 ping ([H][B])
__device__ float g_h0B[H_ * B_];       // h0 pong
__device__ float g_h1A[H_ * B_];       // h1 ping
__device__ float g_h1B[H_ * B_];       // h1 pong
__device__ float g_cst0[H_ * B_];      // c0 init
__device__ float g_cst1[H_ * B_];      // c1 init
__device__ float2 g_partial[32];
__device__ unsigned int g_bar_count = 0;
__device__ volatile unsigned int g_bar_gen = 0;

// ---------------- packed fp32x2 helpers (Blackwell) ----------------------------
__device__ __forceinline__ unsigned long long pk2(float lo, float hi) {
    unsigned long long r;
    asm("mov.b64 %0,{%1,%2};" : "=l"(r) : "f"(lo), "f"(hi));
    return r;
}
__device__ __forceinline__ void ffma2(unsigned long long& d,
                                      unsigned long long a, unsigned long long b) {
    asm("fma.rn.f32x2 %0,%1,%2,%0;" : "+l"(d) : "l"(a), "l"(b));
}
__device__ __forceinline__ float2 up2(unsigned long long v) {
    float2 f;
    asm("mov.b64 {%0,%1},%2;" : "=f"(f.x), "=f"(f.y) : "l"(v));
    return f;
}
__device__ __forceinline__ void cp16(void* sdst, const void* gsrc) {
    unsigned s = (unsigned)__cvta_generic_to_shared(sdst);
    asm volatile("cp.async.cg.shared.global [%0],[%1],16;" :: "r"(s), "l"(gsrc));
}

// ---------------- grid-wide barrier (atomic + generation; known-good) -----------
__device__ __forceinline__ void grid_barrier(int nblocks) {
    __syncthreads();
    if (threadIdx.x == 0) {
        unsigned int gen = g_bar_gen;
        __threadfence();
        if (atomicAdd(&g_bar_count, 1u) == (unsigned)(nblocks - 1)) {
            g_bar_count = 0;
            __threadfence();
            g_bar_gen = gen + 1;
        } else {
            while (g_bar_gen == gen) { __nanosleep(32); }
        }
        __threadfence();
    }
    __syncthreads();
}

// ---------------- build LSTM-0 input (k-major transposed) -----------------------
__global__ void build_inp_kernel(const int* __restrict__ xd,
                                 const float* __restrict__ emb,
                                 const float* __restrict__ Cm,
                                 const float* __restrict__ rep,
                                 const float* __restrict__ seq,
                                 const float* __restrict__ past,
                                 float* __restrict__ inpT) {
    int idx = blockIdx.x * 256 + threadIdx.x;
    if (idx >= M_ * IN0) return;
    int d = idx / M_, col = idx - d * M_;
    int t = col >> 5, b = col & 31;
    float v;
    if (d < ED_) {
        int x = xd[b * S_ + t];
        v = emb[(size_t)x * ED_ + d];
    } else {
        int f = d - ED_;
        float cv;
        if (f < 7)       cv = rep[(b * (S_ + 1) + t) * 7 + f];
        else if (f < 13) cv = seq[(b * (S_ + 1) + t) * 6 + (f - 7)];
        else             cv = past[(b * (S_ + 1) + t) * 6 + (f - 13)];
        v = Cm[(b * S_ + t) * NF_ + f] * cv;
    }
    inpT[idx] = v;
}

// ---------------- generic tiled transpose: out[C][R] = in[R][C]^T ---------------
__global__ void transpose_kernel(const float* __restrict__ in,
                                 float* __restrict__ out, int R, int C) {
    __shared__ float tile[32][33];
    int c0 = blockIdx.x * 32, r0 = blockIdx.y * 32;
    int x = c0 + threadIdx.x;
#pragma unroll
    for (int j = 0; j < 32; j += 8) {
        int y = r0 + threadIdx.y + j;
        if (y < R && x < C) tile[threadIdx.y + j][threadIdx.x] = in[(size_t)y * C + x];
    }
    __syncthreads();
    int x2 = r0 + threadIdx.x;
#pragma unroll
    for (int j = 0; j < 32; j += 8) {
        int y2 = c0 + threadIdx.y + j;
        if (y2 < C && x2 < R) out[(size_t)y2 * R + x2] = tile[threadIdx.x][threadIdx.y + j];
    }
}

// ---------------- init both layers' states into [H][B] --------------------------
__global__ void init_state_kernel(const float* __restrict__ ih,
                                  const float* __restrict__ ic,
                                  float* __restrict__ h0A, float* __restrict__ cst0,
                                  float* __restrict__ h1A, float* __restrict__ cst1) {
    int idx = blockIdx.x * 256 + threadIdx.x;
    if (idx >= H_ * B_) return;
    int j = idx >> 5, b = idx & 31;
    h0A[j * B_ + b]  = ih[b * H_ + j];
    cst0[j * B_ + b] = ic[b * H_ + j];
    h1A[j * B_ + b]  = ih[B_ * H_ + b * H_ + j];
    cst1[j * B_ + b] = ic[B_ * H_ + b * H_ + j];
}

// ---------------- GEMM (k-major inputs): C[M][N] = AT^T * BT + bias1 + bias2 ----
__device__ __forceinline__ void gemm_load_stage(
    float* Abuf, float* Bbuf, const float* AT, const float* BT,
    int s, int m0, int n0, int M, int N, int K, int tid) {
    int off = (s % 3) * 32 * TW;
    int kk = s * 32;
#pragma unroll
    for (int i = 0; i < 4; i++) {
        int task = tid + i * 256;
        int row = task >> 5, c = task & 31;
        float* ad = &Abuf[off + row * TW + c * 4];
        float* bd = &Bbuf[off + row * TW + c * 4];
        if (kk + row < K) {
            cp16(ad, AT + (size_t)(kk + row) * M + m0 + c * 4);
            cp16(bd, BT + (size_t)(kk + row) * N + n0 + c * 4);
        } else {
            *(float4*)ad = make_float4(0.f, 0.f, 0.f, 0.f);
            *(float4*)bd = make_float4(0.f, 0.f, 0.f, 0.f);
        }
    }
    asm volatile("cp.async.commit_group;" ::);
}

__global__ void __launch_bounds__(256) gemm_tt_bias(
    const float* __restrict__ AT, const float* __restrict__ BT,
    const float* __restrict__ bias1, const float* __restrict__ bias2,
    float* __restrict__ Cmat, int M, int N, int K) {
    extern __shared__ float sm[];
    float* Abuf = sm;
    float* Bbuf = sm + 3 * 32 * TW;
    int m0 = blockIdx.y * 128, n0 = blockIdx.x * 128;
    int tid = threadIdx.x;
    int ty = tid >> 4, tx = tid & 15;
    int nk = (K + 31) / 32;

    unsigned long long acc[8][4];
#pragma unroll
    for (int i = 0; i < 8; i++)
#pragma unroll
        for (int j = 0; j < 4; j++) acc[i][j] = 0ull;

    gemm_load_stage(Abuf, Bbuf, AT, BT, 0, m0, n0, M, N, K, tid);
    if (nk > 1) gemm_load_stage(Abuf, Bbuf, AT, BT, 1, m0, n0, M, N, K, tid);

    for (int s = 0; s < nk; s++) {
        if (s + 2 < nk) {
            gemm_load_stage(Abuf, Bbuf, AT, BT, s + 2, m0, n0, M, N, K, tid);
            asm volatile("cp.async.wait_group 2;" ::);
        } else if (s + 1 < nk) {
            asm volatile("cp.async.wait_group 1;" ::);
        } else {
            asm volatile("cp.async.wait_group 0;" ::);
        }
        __syncthreads();
        const float* As = Abuf + (s % 3) * 32 * TW;
        const float* Bs = Bbuf + (s % 3) * 32 * TW;
#pragma unroll 8
        for (int k = 0; k < 32; k++) {
            float4 a0 = *(const float4*)&As[k * TW + ty * 8];
            float4 a1 = *(const float4*)&As[k * TW + ty * 8 + 4];
            ulonglong2 b0 = *(const ulonglong2*)&Bs[k * TW + tx * 8];
            ulonglong2 b1 = *(const ulonglong2*)&Bs[k * TW + tx * 8 + 4];
            unsigned long long aa[8];
            aa[0] = pk2(a0.x, a0.x); aa[1] = pk2(a0.y, a0.y);
            aa[2] = pk2(a0.z, a0.z); aa[3] = pk2(a0.w, a0.w);
            aa[4] = pk2(a1.x, a1.x); aa[5] = pk2(a1.y, a1.y);
            aa[6] = pk2(a1.z, a1.z); aa[7] = pk2(a1.w, a1.w);
#pragma unroll
            for (int i = 0; i < 8; i++) {
                ffma2(acc[i][0], aa[i], b0.x);
                ffma2(acc[i][1], aa[i], b0.y);
                ffma2(acc[i][2], aa[i], b1.x);
                ffma2(acc[i][3], aa[i], b1.y);
            }
        }
        __syncthreads();
    }
#pragma unroll
    for (int i = 0; i < 8; i++) {
        int m = m0 + ty * 8 + i;
#pragma unroll
        for (int j = 0; j < 4; j++) {
            int n = n0 + tx * 8 + j * 2;
            float2 v = up2(acc[i][j]);
            Cmat[(size_t)m * N + n]     = v.x + bias1[n]     + bias2[n];
            Cmat[(size_t)m * N + n + 1] = v.y + bias1[n + 1] + bias2[n + 1];
        }
    }
}
#define GSMEM (6 * 32 * TW * (int)sizeof(float))

// ---------------- fused 2-layer pipelined LSTM scan ------------------------------
// 128 CTAs x 256 threads. CTA owns units jb..jb+3 of BOTH layers.
// smem: W_hh0 / W_ih1 / W_hh1 (16 rows x 512 each) + psum0/psum1.
// Step t: L0 computes h0_t (t<S); L1 computes h1_{t-1} (t>=1) using h0_{t-1}.
__global__ void __launch_bounds__(256, 1) fused_lstm_kernel(
    const float* __restrict__ X0,    // [S*B][4H], row = t*B+b (biases folded)
    const float* __restrict__ Whh0,  // [4H][H]
    const float* __restrict__ Wih1,  // [4H][H]
    const float* __restrict__ Whh1,  // [4H][H]
    const float* __restrict__ bih1,  // [4H]
    const float* __restrict__ bhh1,  // [4H]
    float* __restrict__ h0A, float* __restrict__ h0B,
    float* __restrict__ h1A, float* __restrict__ h1B,
    const float* __restrict__ cst0, const float* __restrict__ cst1,
    float* __restrict__ hall1T)      // [H][S*B]
{
    extern __shared__ float smem[];
    float* W0  = smem;                // [16][512] 32 KB  (W_hh0 rows)
    float* Wi  = smem + 8192;         // [16][512] 32 KB  (W_ih1 rows)
    float* Wh  = smem + 16384;        // [16][512] 32 KB  (W_hh1 rows)
    float* ps0 = smem + 24576;        // [8][16][32] 16 KB
    float* ps1 = smem + 28672;        // [8][16][32] 16 KB

    int tid = threadIdx.x;
    int jb = blockIdx.x * 4;
    int warp = tid >> 5, lane = tid & 31;

    for (int idx = tid; idx < 16 * 512; idx += 256) {
        int r = idx >> 9, k = idx & 511;
        int gr = (r >> 2) * H_ + jb + (r & 3);
        W0[idx] = Whh0[(size_t)gr * H_ + k];
        Wi[idx] = Wih1[(size_t)gr * H_ + k];
        Wh[idx] = Whh1[(size_t)gr * H_ + k];
    }
    int u = warp, b = lane;           // epilogue mapping (tid<128)
    float cc0 = 0.f, cc1 = 0.f;
    float b1i = 0.f, b1f = 0.f, b1g = 0.f, b1o = 0.f;
    if (tid < 128) {
        cc0 = cst0[(jb + u) * B_ + b];
        cc1 = cst1[(jb + u) * B_ + b];
        int gr = jb + u;
        b1i = bih1[gr]          + bhh1[gr];
        b1f = bih1[H_ + gr]     + bhh1[H_ + gr];
        b1g = bih1[2 * H_ + gr] + bhh1[2 * H_ + gr];
        b1o = bih1[3 * H_ + gr] + bhh1[3 * H_ + gr];
    }
    __syncthreads();

    const int k0 = warp * 64;
    for (int t = 0; t <= S_; t++) {
        const bool doL0 = (t < S_);
        const bool doL1 = (t >= 1);
        // h0 ping-pong (same scheme as before): read h0_{t-1}, write h0_t
        const float* h0cur = (t & 1) ? h0B : h0A;
        float* h0nxt       = (t & 1) ? h0A : h0B;
        // h1 ping-pong indexed by s = t-1: read h1_{t-2}, write h1_{t-1}
        const float* h1cur = ((t - 1) & 1) ? h1B : h1A;
        float* h1nxt       = ((t - 1) & 1) ? h1A : h1B;

        // X0 prefetch for layer-0 epilogue
        float xi = 0.f, xf = 0.f, xg = 0.f, xo = 0.f;
        if (doL0 && tid < 128) {
            const float* xrow = X0 + (size_t)(t * B_ + b) * G4 + jb + u;
            xi = xrow[0]; xf = xrow[512]; xg = xrow[1024]; xo = xrow[1536];
        }

        const float* hp0 = h0cur + k0 * B_ + lane;

        // ---- phase A: layer-0 recurrence (W_hh0 @ h0_{t-1}) ----
        if (doL0) {
            unsigned long long a0[16];
#pragma unroll
            for (int r = 0; r < 16; r++) a0[r] = 0ull;
#pragma unroll
            for (int kb = 0; kb < 8; kb++) {
                float h0 = __ldcg(hp0 + (kb * 8 + 0) * B_);
                float h1 = __ldcg(hp0 + (kb * 8 + 1) * B_);
                float h2 = __ldcg(hp0 + (kb * 8 + 2) * B_);
                float h3 = __ldcg(hp0 + (kb * 8 + 3) * B_);
                float h4 = __ldcg(hp0 + (kb * 8 + 4) * B_);
                float h5 = __ldcg(hp0 + (kb * 8 + 5) * B_);
                float h6 = __ldcg(hp0 + (kb * 8 + 6) * B_);
                float h7 = __ldcg(hp0 + (kb * 8 + 7) * B_);
                unsigned long long hv0 = pk2(h0, h1), hv1 = pk2(h2, h3);
                unsigned long long hv2 = pk2(h4, h5), hv3 = pk2(h6, h7);
                const float* wb = W0 + k0 + kb * 8;
#pragma unroll
                for (int r = 0; r < 16; r++) {
                    ulonglong2 w0 = *(const ulonglong2*)(wb + r * 512);
                    ulonglong2 w1 = *(const ulonglong2*)(wb + r * 512 + 4);
                    ffma2(a0[r], hv0, w0.x);
                    ffma2(a0[r], hv1, w0.y);
                    ffma2(a0[r], hv2, w1.x);
                    ffma2(a0[r], hv3, w1.y);
                }
            }
#pragma unroll
            for (int r = 0; r < 16; r++) {
                float2 p = up2(a0[r]);
                ps0[(warp * 16 + r) * 32 + lane] = p.x + p.y;
            }
        }

        // ---- phase B: layer-1 (W_ih1 @ h0_{t-1} + W_hh1 @ h1_{t-2}) ----
        if (doL1) {
            unsigned long long a1[16];
#pragma unroll
            for (int r = 0; r < 16; r++) a1[r] = 0ull;
#pragma unroll
            for (int kb = 0; kb < 8; kb++) {
                float h0 = __ldcg(hp0 + (kb * 8 + 0) * B_);
                float h1 = __ldcg(hp0 + (kb * 8 + 1) * B_);
                float h2 = __ldcg(hp0 + (kb * 8 + 2) * B_);
                float h3 = __ldcg(hp0 + (kb * 8 + 3) * B_);
                float h4 = __ldcg(hp0 + (kb * 8 + 4) * B_);
                float h5 = __ldcg(hp0 + (kb * 8 + 5) * B_);
                float h6 = __ldcg(hp0 + (kb * 8 + 6) * B_);
                float h7 = __ldcg(hp0 + (kb * 8 + 7) * B_);
                unsigned long long hv0 = pk2(h0, h1), hv1 = pk2(h2, h3);
                unsigned long long hv2 = pk2(h4, h5), hv3 = pk2(h6, h7);
                const float* wb = Wi + k0 + kb * 8;
#pragma unroll
                for (int r = 0; r < 16; r++) {
                    ulonglong2 w0 = *(const ulonglong2*)(wb + r * 512);
                    ulonglong2 w1 = *(const ulonglong2*)(wb + r * 512 + 4);
                    ffma2(a1[r], hv0, w0.x);
                    ffma2(a1[r], hv1, w0.y);
                    ffma2(a1[r], hv2, w1.x);
                    ffma2(a1[r], hv3, w1.y);
                }
            }
            const float* hp1 = h1cur + k0 * B_ + lane;
#pragma unroll
            for (int kb = 0; kb < 8; kb++) {
                float h0 = __ldcg(hp1 + (kb * 8 + 0) * B_);
                float h1 = __ldcg(hp1 + (kb * 8 + 1) * B_);
                float h2 = __ldcg(hp1 + (kb * 8 + 2) * B_);
                float h3 = __ldcg(hp1 + (kb * 8 + 3) * B_);
                float h4 = __ldcg(hp1 + (kb * 8 + 4) * B_);
                float h5 = __ldcg(hp1 + (kb * 8 + 5) * B_);
                float h6 = __ldcg(hp1 + (kb * 8 + 6) * B_);
                float h7 = __ldcg(hp1 + (kb * 8 + 7) * B_);
                unsigned long long hv0 = pk2(h0, h1), hv1 = pk2(h2, h3);
                unsigned long long hv2 = pk2(h4, h5), hv3 = pk2(h6, h7);
                const float* wb = Wh + k0 + kb * 8;
#pragma unroll
                for (int r = 0; r < 16; r++) {
                    ulonglong2 w0 = *(const ulonglong2*)(wb + r * 512);
                    ulonglong2 w1 = *(const ulonglong2*)(wb + r * 512 + 4);
                    ffma2(a1[r], hv0, w0.x);
                    ffma2(a1[r], hv1, w0.y);
                    ffma2(a1[r], hv2, w1.x);
                    ffma2(a1[r], hv3, w1.y);
                }
            }
#pragma unroll
            for (int r = 0; r < 16; r++) {
                float2 p = up2(a1[r]);
                ps1[(warp * 16 + r) * 32 + lane] = p.x + p.y;
            }
        }
        __syncthreads();

        // ---- epilogue on 128 threads ----
        if (tid < 128) {
            if (doL0) {
                float s_i = xi, s_f = xf, s_g = xg, s_o = xo;
#pragma unroll
                for (int w = 0; w < 8; w++) {
                    s_i += ps0[(w * 16 + 0  + u) * 32 + b];
                    s_f += ps0[(w * 16 + 4  + u) * 32 + b];
                    s_g += ps0[(w * 16 + 8  + u) * 32 + b];
                    s_o += ps0[(w * 16 + 12 + u) * 32 + b];
                }
                float ig = 1.f / (1.f + expf(-s_i));
                float fg = 1.f / (1.f + expf(-s_f));
                float og = 1.f / (1.f + expf(-s_o));
                cc0 = fg * cc0 + ig * tanhf(s_g);
                float hv = og * tanhf(cc0);
                __stcg(&h0nxt[(jb + u) * B_ + b], hv);
            }
            if (doL1) {
                float s_i = b1i, s_f = b1f, s_g = b1g, s_o = b1o;
#pragma unroll
                for (int w = 0; w < 8; w++) {
                    s_i += ps1[(w * 16 + 0  + u) * 32 + b];
                    s_f += ps1[(w * 16 + 4  + u) * 32 + b];
                    s_g += ps1[(w * 16 + 8  + u) * 32 + b];
                    s_o += ps1[(w * 16 + 12 + u) * 32 + b];
                }
                float ig = 1.f / (1.f + expf(-s_i));
                float fg = 1.f / (1.f + expf(-s_f));
                float og = 1.f / (1.f + expf(-s_o));
                cc1 = fg * cc1 + ig * tanhf(s_g);
                float hv = og * tanhf(cc1);
                __stcg(&h1nxt[(jb + u) * B_ + b], hv);
                hall1T[(size_t)(jb + u) * M_ + (t - 1) * B_ + b] = hv;
            }
        }
        if (t < S_) grid_barrier(NCTA);   // last iteration needs no barrier
    }
}
#define FSMEM ((3 * 16 * 512 + 2 * 8 * 16 * 32) * (int)sizeof(float))

// ---------------- gathered prediction + BCE partials ----------------------------
__global__ void pred_kernel(const float* __restrict__ hallT,
                            const float* __restrict__ Wp,
                            const float* __restrict__ bp,
                            const int* __restrict__ qt,
                            const float* __restrict__ target,
                            const float* __restrict__ Cm,
                            const float* __restrict__ rep,
                            const float* __restrict__ seq,
                            const float* __restrict__ past,
                            float* __restrict__ out,
                            float2* __restrict__ partial) {
    int col = blockIdx.x * 256 + threadIdx.x;     // t*B+b ordering
    int b = col & 31, s = col >> 5;
    int r = b * S_ + s;
    int q = qt[r];
    const float* wrow = Wp + (size_t)q * PD_;
    const float* hc = hallT + col;
    float acc = bp[q];
#pragma unroll 8
    for (int d = 0; d < H_; d++) acc = fmaf(hc[(size_t)d * M_], wrow[d], acc);
#pragma unroll
    for (int f = 0; f < NF_; f++) {
        float cv;
        if (f < 7)       cv = rep[(b * (S_ + 1) + s + 1) * 7 + f];
        else if (f < 13) cv = seq[(b * (S_ + 1) + s + 1) * 6 + (f - 7)];
        else             cv = past[(b * (S_ + 1) + s + 1) * 6 + (f - 13)];
        float pi = Cm[(b * S_ + s) * NF_ + f] * cv;
        acc = fmaf(pi, wrow[H_ + f], acc);
    }
    float m = (q > 0) ? 1.f : 0.f;
    float tt = target[r];
    float sg = 1.f / (1.f + expf(-acc));
    out[1 + r] = sg * m;
    out[1 + M_ + r] = tt * m;
    float l = fmaxf(acc, 0.f) - acc * tt + log1pf(expf(-fabsf(acc)));

    __shared__ float sb[256], sm2[256];
    sb[threadIdx.x] = l * m;
    sm2[threadIdx.x] = m;
    __syncthreads();
    for (int st = 128; st > 0; st >>= 1) {
        if (threadIdx.x < st) {
            sb[threadIdx.x] += sb[threadIdx.x + st];
            sm2[threadIdx.x] += sm2[threadIdx.x + st];
        }
        __syncthreads();
    }
    if (threadIdx.x == 0) partial[blockIdx.x] = make_float2(sb[0], sm2[0]);
}

__global__ void finalize_kernel(const float2* __restrict__ partial, int n,
                                float* __restrict__ out) {
    __shared__ float sa[32], sc[32];
    float a = 0.f, c = 0.f;
    if (threadIdx.x < n) { float2 p = partial[threadIdx.x]; a = p.x; c = p.y; }
    sa[threadIdx.x] = a; sc[threadIdx.x] = c;
    __syncthreads();
    for (int s = 16; s > 0; s >>= 1) {
        if (threadIdx.x < s) {
            sa[threadIdx.x] += sa[threadIdx.x + s];
            sc[threadIdx.x] += sc[threadIdx.x + s];
        }
        __syncthreads();
    }
    if (threadIdx.x == 0) out[0] = sa[0] / sc[0];
}

// ---------------- launch --------------------------------------------------------
extern "C" void kernel_launch(void* const* d_in, const int* in_sizes, int n_in,
                              void* d_out, int out_size) {
    const int*   x_data = (const int*)d_in[0];
    const int*   q_t    = (const int*)d_in[1];
    const float* target = (const float*)d_in[2];
    const float* rep    = (const float*)d_in[3];
    const float* past   = (const float*)d_in[4];
    const float* seq    = (const float*)d_in[5];
    const float* embed  = (const float*)d_in[6];
    const float* W_ih0  = (const float*)d_in[7];
    const float* W_hh0  = (const float*)d_in[8];
    const float* b_ih0  = (const float*)d_in[9];
    const float* b_hh0  = (const float*)d_in[10];
    const float* W_ih1  = (const float*)d_in[11];
    const float* W_hh1  = (const float*)d_in[12];
    const float* b_ih1  = (const float*)d_in[13];
    const float* b_hh1  = (const float*)d_in[14];
    const float* W_pred = (const float*)d_in[15];
    const float* b_pred = (const float*)d_in[16];
    const float* Cm     = (const float*)d_in[17];
    const float* init_h = (const float*)d_in[18];
    const float* init_c = (const float*)d_in[19];
    float* out = (float*)d_out;

    float *p_inpT, *p_X, *p_h1T, *p_WT, *p_h0A, *p_h0B, *p_h1A, *p_h1B;
    float *p_c0, *p_c1;
    float2* p_part;
    cudaGetSymbolAddress((void**)&p_inpT, g_inpT);
    cudaGetSymbolAddress((void**)&p_X,    g_X);
    cudaGetSymbolAddress((void**)&p_h1T,  g_hall1T);
    cudaGetSymbolAddress((void**)&p_WT,   g_WT);
    cudaGetSymbolAddress((void**)&p_h0A,  g_h0A);
    cudaGetSymbolAddress((void**)&p_h0B,  g_h0B);
    cudaGetSymbolAddress((void**)&p_h1A,  g_h1A);
    cudaGetSymbolAddress((void**)&p_h1B,  g_h1B);
    cudaGetSymbolAddress((void**)&p_c0,   g_cst0);
    cudaGetSymbolAddress((void**)&p_c1,   g_cst1);
    cudaGetSymbolAddress((void**)&p_part, g_partial);

    cudaFuncSetAttribute(gemm_tt_bias,
                         cudaFuncAttributeMaxDynamicSharedMemorySize, GSMEM);
    cudaFuncSetAttribute(fused_lstm_kernel,
                         cudaFuncAttributeMaxDynamicSharedMemorySize, FSMEM);

    // 1) build LSTM-0 input rows (k-major)
    build_inp_kernel<<<(M_ * IN0 + 255) / 256, 256>>>(x_data, embed, Cm, rep, seq,
                                                      past, p_inpT);
    // 2) X0 = inp @ W_ih0^T + b_ih0 + b_hh0
    transpose_kernel<<<dim3((IN0 + 31) / 32, G4 / 32), dim3(32, 8)>>>(W_ih0, p_WT,
                                                                      G4, IN0);
    gemm_tt_bias<<<dim3(G4 / 128, M_ / 128), 256, GSMEM>>>(p_inpT, p_WT, b_ih0,
                                                           b_hh0, p_X, M_, G4, IN0);
    // 3) init both layers' states
    init_state_kernel<<<(H_ * B_ + 255) / 256, 256>>>(init_h, init_c, p_h0A, p_c0,
                                                      p_h1A, p_c1);
    // 4) fused pipelined 2-layer scan (201 steps)
    fused_lstm_kernel<<<NCTA, 256, FSMEM>>>(p_X, W_hh0, W_ih1, W_hh1, b_ih1,
                                            b_hh1, p_h0A, p_h0B, p_h1A, p_h1B,
                                            p_c0, p_c1, p_h1T);
    // 5) gathered prediction head + BCE partials
    pred_kernel<<<M_ / 256, 256>>>(p_h1T, W_pred, b_pred, q_t, target, Cm, rep,
                                   seq, past, out, p_part);
    // 6) loss
    finalize_kernel<<<1, 32>>>(p_part, M_ / 256, out);
}

// round 12
// speedup vs baseline: 1.8016x; 1.0249x over previous
#include <cuda_runtime.h>
#include <math.h>

// R12 = R11 + merged h0 pass in the fused scan (W0 and Wi accumulate off the
// same h0 load stream; 192 -> 128 loads/warp/step, 3 -> 2 dependent chains).

#define B_   32
#define S_   200
#define H_   512
#define G4   2048
#define ED_  256
#define NF_  19
#define IN0  275
#define M_   6400
#define PD_  531
#define NCTA 128
#define TW   132                      // smem tile row stride (floats)

// ---------------- scratch (static device memory; no allocation) ----------------
__device__ float g_inpT[IN0 * M_];     // LSTM-0 input, k-major [IN0][M]
__device__ float g_X[M_ * G4];         // X0 = inp@Wih0^T + biases (row-major)
__device__ float g_hall1T[H_ * M_];    // layer-1 hidden, k-major [H][M]
__device__ float g_WT[512 * G4];       // transposed W_ih0
__device__ float g_h0A[H_ * B_];       // h0 ping ([H][B])
__device__ float g_h0B[H_ * B_];       // h0 pong
__device__ float g_h1A[H_ * B_];       // h1 ping
__device__ float g_h1B[H_ * B_];       // h1 pong
__device__ float g_cst0[H_ * B_];      // c0 init
__device__ float g_cst1[H_ * B_];      // c1 init
__device__ float2 g_partial[32];
__device__ unsigned int g_bar_count = 0;
__device__ volatile unsigned int g_bar_gen = 0;

// ---------------- packed fp32x2 helpers (Blackwell) ----------------------------
__device__ __forceinline__ unsigned long long pk2(float lo, float hi) {
    unsigned long long r;
    asm("mov.b64 %0,{%1,%2};" : "=l"(r) : "f"(lo), "f"(hi));
    return r;
}
__device__ __forceinline__ void ffma2(unsigned long long& d,
                                      unsigned long long a, unsigned long long b) {
    asm("fma.rn.f32x2 %0,%1,%2,%0;" : "+l"(d) : "l"(a), "l"(b));
}
__device__ __forceinline__ float2 up2(unsigned long long v) {
    float2 f;
    asm("mov.b64 {%0,%1},%2;" : "=f"(f.x), "=f"(f.y) : "l"(v));
    return f;
}
__device__ __forceinline__ void cp16(void* sdst, const void* gsrc) {
    unsigned s = (unsigned)__cvta_generic_to_shared(sdst);
    asm volatile("cp.async.cg.shared.global [%0],[%1],16;" :: "r"(s), "l"(gsrc));
}

// ---------------- grid-wide barrier (atomic + generation; known-good) -----------
__device__ __forceinline__ void grid_barrier(int nblocks) {
    __syncthreads();
    if (threadIdx.x == 0) {
        unsigned int gen = g_bar_gen;
        __threadfence();
        if (atomicAdd(&g_bar_count, 1u) == (unsigned)(nblocks - 1)) {
            g_bar_count = 0;
            __threadfence();
            g_bar_gen = gen + 1;
        } else {
            while (g_bar_gen == gen) { __nanosleep(32); }
        }
        __threadfence();
    }
    __syncthreads();
}

// ---------------- build LSTM-0 input (k-major transposed) -----------------------
__global__ void build_inp_kernel(const int* __restrict__ xd,
                                 const float* __restrict__ emb,
                                 const float* __restrict__ Cm,
                                 const float* __restrict__ rep,
                                 const float* __restrict__ seq,
                                 const float* __restrict__ past,
                                 float* __restrict__ inpT) {
    int idx = blockIdx.x * 256 + threadIdx.x;
    if (idx >= M_ * IN0) return;
    int d = idx / M_, col = idx - d * M_;
    int t = col >> 5, b = col & 31;
    float v;
    if (d < ED_) {
        int x = xd[b * S_ + t];
        v = emb[(size_t)x * ED_ + d];
    } else {
        int f = d - ED_;
        float cv;
        if (f < 7)       cv = rep[(b * (S_ + 1) + t) * 7 + f];
        else if (f < 13) cv = seq[(b * (S_ + 1) + t) * 6 + (f - 7)];
        else             cv = past[(b * (S_ + 1) + t) * 6 + (f - 13)];
        v = Cm[(b * S_ + t) * NF_ + f] * cv;
    }
    inpT[idx] = v;
}

// ---------------- generic tiled transpose: out[C][R] = in[R][C]^T ---------------
__global__ void transpose_kernel(const float* __restrict__ in,
                                 float* __restrict__ out, int R, int C) {
    __shared__ float tile[32][33];
    int c0 = blockIdx.x * 32, r0 = blockIdx.y * 32;
    int x = c0 + threadIdx.x;
#pragma unroll
    for (int j = 0; j < 32; j += 8) {
        int y = r0 + threadIdx.y + j;
        if (y < R && x < C) tile[threadIdx.y + j][threadIdx.x] = in[(size_t)y * C + x];
    }
    __syncthreads();
    int x2 = r0 + threadIdx.x;
#pragma unroll
    for (int j = 0; j < 32; j += 8) {
        int y2 = c0 + threadIdx.y + j;
        if (y2 < C && x2 < R) out[(size_t)y2 * R + x2] = tile[threadIdx.x][threadIdx.y + j];
    }
}

// ---------------- init both layers' states into [H][B] --------------------------
__global__ void init_state_kernel(const float* __restrict__ ih,
                                  const float* __restrict__ ic,
                                  float* __restrict__ h0A, float* __restrict__ cst0,
                                  float* __restrict__ h1A, float* __restrict__ cst1) {
    int idx = blockIdx.x * 256 + threadIdx.x;
    if (idx >= H_ * B_) return;
    int j = idx >> 5, b = idx & 31;
    h0A[j * B_ + b]  = ih[b * H_ + j];
    cst0[j * B_ + b] = ic[b * H_ + j];
    h1A[j * B_ + b]  = ih[B_ * H_ + b * H_ + j];
    cst1[j * B_ + b] = ic[B_ * H_ + b * H_ + j];
}

// ---------------- GEMM (k-major inputs): C[M][N] = AT^T * BT + bias1 + bias2 ----
__device__ __forceinline__ void gemm_load_stage(
    float* Abuf, float* Bbuf, const float* AT, const float* BT,
    int s, int m0, int n0, int M, int N, int K, int tid) {
    int off = (s % 3) * 32 * TW;
    int kk = s * 32;
#pragma unroll
    for (int i = 0; i < 4; i++) {
        int task = tid + i * 256;
        int row = task >> 5, c = task & 31;
        float* ad = &Abuf[off + row * TW + c * 4];
        float* bd = &Bbuf[off + row * TW + c * 4];
        if (kk + row < K) {
            cp16(ad, AT + (size_t)(kk + row) * M + m0 + c * 4);
            cp16(bd, BT + (size_t)(kk + row) * N + n0 + c * 4);
        } else {
            *(float4*)ad = make_float4(0.f, 0.f, 0.f, 0.f);
            *(float4*)bd = make_float4(0.f, 0.f, 0.f, 0.f);
        }
    }
    asm volatile("cp.async.commit_group;" ::);
}

__global__ void __launch_bounds__(256) gemm_tt_bias(
    const float* __restrict__ AT, const float* __restrict__ BT,
    const float* __restrict__ bias1, const float* __restrict__ bias2,
    float* __restrict__ Cmat, int M, int N, int K) {
    extern __shared__ float sm[];
    float* Abuf = sm;
    float* Bbuf = sm + 3 * 32 * TW;
    int m0 = blockIdx.y * 128, n0 = blockIdx.x * 128;
    int tid = threadIdx.x;
    int ty = tid >> 4, tx = tid & 15;
    int nk = (K + 31) / 32;

    unsigned long long acc[8][4];
#pragma unroll
    for (int i = 0; i < 8; i++)
#pragma unroll
        for (int j = 0; j < 4; j++) acc[i][j] = 0ull;

    gemm_load_stage(Abuf, Bbuf, AT, BT, 0, m0, n0, M, N, K, tid);
    if (nk > 1) gemm_load_stage(Abuf, Bbuf, AT, BT, 1, m0, n0, M, N, K, tid);

    for (int s = 0; s < nk; s++) {
        if (s + 2 < nk) {
            gemm_load_stage(Abuf, Bbuf, AT, BT, s + 2, m0, n0, M, N, K, tid);
            asm volatile("cp.async.wait_group 2;" ::);
        } else if (s + 1 < nk) {
            asm volatile("cp.async.wait_group 1;" ::);
        } else {
            asm volatile("cp.async.wait_group 0;" ::);
        }
        __syncthreads();
        const float* As = Abuf + (s % 3) * 32 * TW;
        const float* Bs = Bbuf + (s % 3) * 32 * TW;
#pragma unroll 8
        for (int k = 0; k < 32; k++) {
            float4 a0 = *(const float4*)&As[k * TW + ty * 8];
            float4 a1 = *(const float4*)&As[k * TW + ty * 8 + 4];
            ulonglong2 b0 = *(const ulonglong2*)&Bs[k * TW + tx * 8];
            ulonglong2 b1 = *(const ulonglong2*)&Bs[k * TW + tx * 8 + 4];
            unsigned long long aa[8];
            aa[0] = pk2(a0.x, a0.x); aa[1] = pk2(a0.y, a0.y);
            aa[2] = pk2(a0.z, a0.z); aa[3] = pk2(a0.w, a0.w);
            aa[4] = pk2(a1.x, a1.x); aa[5] = pk2(a1.y, a1.y);
            aa[6] = pk2(a1.z, a1.z); aa[7] = pk2(a1.w, a1.w);
#pragma unroll
            for (int i = 0; i < 8; i++) {
                ffma2(acc[i][0], aa[i], b0.x);
                ffma2(acc[i][1], aa[i], b0.y);
                ffma2(acc[i][2], aa[i], b1.x);
                ffma2(acc[i][3], aa[i], b1.y);
            }
        }
        __syncthreads();
    }
#pragma unroll
    for (int i = 0; i < 8; i++) {
        int m = m0 + ty * 8 + i;
#pragma unroll
        for (int j = 0; j < 4; j++) {
            int n = n0 + tx * 8 + j * 2;
            float2 v = up2(acc[i][j]);
            Cmat[(size_t)m * N + n]     = v.x + bias1[n]     + bias2[n];
            Cmat[(size_t)m * N + n + 1] = v.y + bias1[n + 1] + bias2[n + 1];
        }
    }
}
#define GSMEM (6 * 32 * TW * (int)sizeof(float))

// ---------------- fused 2-layer pipelined LSTM scan ------------------------------
// 128 CTAs x 256 threads. CTA owns units jb..jb+3 of BOTH layers.
// Step t: L0 computes h0_t (t<S); L1 computes h1_{t-1} (t>=1) using h0_{t-1}.
// Single h0 pass feeds BOTH W_hh0 (->a0) and W_ih1 (->a1).
__global__ void __launch_bounds__(256, 1) fused_lstm_kernel(
    const float* __restrict__ X0,    // [S*B][4H], row = t*B+b (biases folded)
    const float* __restrict__ Whh0,  // [4H][H]
    const float* __restrict__ Wih1,  // [4H][H]
    const float* __restrict__ Whh1,  // [4H][H]
    const float* __restrict__ bih1,  // [4H]
    const float* __restrict__ bhh1,  // [4H]
    float* __restrict__ h0A, float* __restrict__ h0B,
    float* __restrict__ h1A, float* __restrict__ h1B,
    const float* __restrict__ cst0, const float* __restrict__ cst1,
    float* __restrict__ hall1T)      // [H][S*B]
{
    extern __shared__ float smem[];
    float* W0  = smem;                // [16][512] 32 KB  (W_hh0 rows)
    float* Wi  = smem + 8192;         // [16][512] 32 KB  (W_ih1 rows)
    float* Wh  = smem + 16384;        // [16][512] 32 KB  (W_hh1 rows)
    float* ps0 = smem + 24576;        // [8][16][32] 16 KB
    float* ps1 = smem + 28672;        // [8][16][32] 16 KB

    int tid = threadIdx.x;
    int jb = blockIdx.x * 4;
    int warp = tid >> 5, lane = tid & 31;

    for (int idx = tid; idx < 16 * 512; idx += 256) {
        int r = idx >> 9, k = idx & 511;
        int gr = (r >> 2) * H_ + jb + (r & 3);
        W0[idx] = Whh0[(size_t)gr * H_ + k];
        Wi[idx] = Wih1[(size_t)gr * H_ + k];
        Wh[idx] = Whh1[(size_t)gr * H_ + k];
    }
    int u = warp, b = lane;           // epilogue mapping (tid<128)
    float cc0 = 0.f, cc1 = 0.f;
    float b1i = 0.f, b1f = 0.f, b1g = 0.f, b1o = 0.f;
    if (tid < 128) {
        cc0 = cst0[(jb + u) * B_ + b];
        cc1 = cst1[(jb + u) * B_ + b];
        int gr = jb + u;
        b1i = bih1[gr]          + bhh1[gr];
        b1f = bih1[H_ + gr]     + bhh1[H_ + gr];
        b1g = bih1[2 * H_ + gr] + bhh1[2 * H_ + gr];
        b1o = bih1[3 * H_ + gr] + bhh1[3 * H_ + gr];
    }
    __syncthreads();

    const int k0 = warp * 64;
    for (int t = 0; t <= S_; t++) {
        const bool doL0 = (t < S_);
        const bool doL1 = (t >= 1);
        const float* h0cur = (t & 1) ? h0B : h0A;
        float* h0nxt       = (t & 1) ? h0A : h0B;
        const float* h1cur = ((t - 1) & 1) ? h1B : h1A;
        float* h1nxt       = ((t - 1) & 1) ? h1A : h1B;

        // X0 prefetch for layer-0 epilogue
        float xi = 0.f, xf = 0.f, xg = 0.f, xo = 0.f;
        if (doL0 && tid < 128) {
            const float* xrow = X0 + (size_t)(t * B_ + b) * G4 + jb + u;
            xi = xrow[0]; xf = xrow[512]; xg = xrow[1024]; xo = xrow[1536];
        }

        unsigned long long a0[16], a1[16];
#pragma unroll
        for (int r = 0; r < 16; r++) { a0[r] = 0ull; a1[r] = 0ull; }

        // ---- merged h0 pass: a0 += W0@h0, a1 += Wi@h0 (same hv stream) ----
        {
            const float* hp0 = h0cur + k0 * B_ + lane;
#pragma unroll
            for (int kb = 0; kb < 8; kb++) {
                float h0 = __ldcg(hp0 + (kb * 8 + 0) * B_);
                float h1 = __ldcg(hp0 + (kb * 8 + 1) * B_);
                float h2 = __ldcg(hp0 + (kb * 8 + 2) * B_);
                float h3 = __ldcg(hp0 + (kb * 8 + 3) * B_);
                float h4 = __ldcg(hp0 + (kb * 8 + 4) * B_);
                float h5 = __ldcg(hp0 + (kb * 8 + 5) * B_);
                float h6 = __ldcg(hp0 + (kb * 8 + 6) * B_);
                float h7 = __ldcg(hp0 + (kb * 8 + 7) * B_);
                unsigned long long hv0 = pk2(h0, h1), hv1 = pk2(h2, h3);
                unsigned long long hv2 = pk2(h4, h5), hv3 = pk2(h6, h7);
                const float* wb0 = W0 + k0 + kb * 8;
                const float* wbi = Wi + k0 + kb * 8;
#pragma unroll
                for (int r = 0; r < 16; r++) {
                    ulonglong2 w0 = *(const ulonglong2*)(wb0 + r * 512);
                    ulonglong2 w1 = *(const ulonglong2*)(wb0 + r * 512 + 4);
                    ffma2(a0[r], hv0, w0.x);
                    ffma2(a0[r], hv1, w0.y);
                    ffma2(a0[r], hv2, w1.x);
                    ffma2(a0[r], hv3, w1.y);
                    ulonglong2 v0 = *(const ulonglong2*)(wbi + r * 512);
                    ulonglong2 v1 = *(const ulonglong2*)(wbi + r * 512 + 4);
                    ffma2(a1[r], hv0, v0.x);
                    ffma2(a1[r], hv1, v0.y);
                    ffma2(a1[r], hv2, v1.x);
                    ffma2(a1[r], hv3, v1.y);
                }
            }
        }
        // ---- h1 pass: a1 += Wh@h1 ----
        if (doL1) {
            const float* hp1 = h1cur + k0 * B_ + lane;
#pragma unroll
            for (int kb = 0; kb < 8; kb++) {
                float h0 = __ldcg(hp1 + (kb * 8 + 0) * B_);
                float h1 = __ldcg(hp1 + (kb * 8 + 1) * B_);
                float h2 = __ldcg(hp1 + (kb * 8 + 2) * B_);
                float h3 = __ldcg(hp1 + (kb * 8 + 3) * B_);
                float h4 = __ldcg(hp1 + (kb * 8 + 4) * B_);
                float h5 = __ldcg(hp1 + (kb * 8 + 5) * B_);
                float h6 = __ldcg(hp1 + (kb * 8 + 6) * B_);
                float h7 = __ldcg(hp1 + (kb * 8 + 7) * B_);
                unsigned long long hv0 = pk2(h0, h1), hv1 = pk2(h2, h3);
                unsigned long long hv2 = pk2(h4, h5), hv3 = pk2(h6, h7);
                const float* wb = Wh + k0 + kb * 8;
#pragma unroll
                for (int r = 0; r < 16; r++) {
                    ulonglong2 w0 = *(const ulonglong2*)(wb + r * 512);
                    ulonglong2 w1 = *(const ulonglong2*)(wb + r * 512 + 4);
                    ffma2(a1[r], hv0, w0.x);
                    ffma2(a1[r], hv1, w0.y);
                    ffma2(a1[r], hv2, w1.x);
                    ffma2(a1[r], hv3, w1.y);
                }
            }
        }
#pragma unroll
        for (int r = 0; r < 16; r++) {
            float2 p0 = up2(a0[r]);
            ps0[(warp * 16 + r) * 32 + lane] = p0.x + p0.y;
            float2 p1 = up2(a1[r]);
            ps1[(warp * 16 + r) * 32 + lane] = p1.x + p1.y;
        }
        __syncthreads();

        // ---- epilogue on 128 threads ----
        if (tid < 128) {
            if (doL0) {
                float s_i = xi, s_f = xf, s_g = xg, s_o = xo;
#pragma unroll
                for (int w = 0; w < 8; w++) {
                    s_i += ps0[(w * 16 + 0  + u) * 32 + b];
                    s_f += ps0[(w * 16 + 4  + u) * 32 + b];
                    s_g += ps0[(w * 16 + 8  + u) * 32 + b];
                    s_o += ps0[(w * 16 + 12 + u) * 32 + b];
                }
                float ig = 1.f / (1.f + expf(-s_i));
                float fg = 1.f / (1.f + expf(-s_f));
                float og = 1.f / (1.f + expf(-s_o));
                cc0 = fg * cc0 + ig * tanhf(s_g);
                float hv = og * tanhf(cc0);
                __stcg(&h0nxt[(jb + u) * B_ + b], hv);
            }
            if (doL1) {
                float s_i = b1i, s_f = b1f, s_g = b1g, s_o = b1o;
#pragma unroll
                for (int w = 0; w < 8; w++) {
                    s_i += ps1[(w * 16 + 0  + u) * 32 + b];
                    s_f += ps1[(w * 16 + 4  + u) * 32 + b];
                    s_g += ps1[(w * 16 + 8  + u) * 32 + b];
                    s_o += ps1[(w * 16 + 12 + u) * 32 + b];
                }
                float ig = 1.f / (1.f + expf(-s_i));
                float fg = 1.f / (1.f + expf(-s_f));
                float og = 1.f / (1.f + expf(-s_o));
                cc1 = fg * cc1 + ig * tanhf(s_g);
                float hv = og * tanhf(cc1);
                __stcg(&h1nxt[(jb + u) * B_ + b], hv);
                hall1T[(size_t)(jb + u) * M_ + (t - 1) * B_ + b] = hv;
            }
        }
        if (t < S_) grid_barrier(NCTA);   // last iteration needs no barrier
    }
}
#define FSMEM ((3 * 16 * 512 + 2 * 8 * 16 * 32) * (int)sizeof(float))

// ---------------- gathered prediction + BCE partials ----------------------------
__global__ void pred_kernel(const float* __restrict__ hallT,
                            const float* __restrict__ Wp,
                            const float* __restrict__ bp,
                            const int* __restrict__ qt,
                            const float* __restrict__ target,
                            const float* __restrict__ Cm,
                            const float* __restrict__ rep,
                            const float* __restrict__ seq,
                            const float* __restrict__ past,
                            float* __restrict__ out,
                            float2* __restrict__ partial) {
    int col = blockIdx.x * 256 + threadIdx.x;     // t*B+b ordering
    int b = col & 31, s = col >> 5;
    int r = b * S_ + s;
    int q = qt[r];
    const float* wrow = Wp + (size_t)q * PD_;
    const float* hc = hallT + col;
    float acc = bp[q];
#pragma unroll 8
    for (int d = 0; d < H_; d++) acc = fmaf(hc[(size_t)d * M_], wrow[d], acc);
#pragma unroll
    for (int f = 0; f < NF_; f++) {
        float cv;
        if (f < 7)       cv = rep[(b * (S_ + 1) + s + 1) * 7 + f];
        else if (f < 13) cv = seq[(b * (S_ + 1) + s + 1) * 6 + (f - 7)];
        else             cv = past[(b * (S_ + 1) + s + 1) * 6 + (f - 13)];
        float pi = Cm[(b * S_ + s) * NF_ + f] * cv;
        acc = fmaf(pi, wrow[H_ + f], acc);
    }
    float m = (q > 0) ? 1.f : 0.f;
    float tt = target[r];
    float sg = 1.f / (1.f + expf(-acc));
    out[1 + r] = sg * m;
    out[1 + M_ + r] = tt * m;
    float l = fmaxf(acc, 0.f) - acc * tt + log1pf(expf(-fabsf(acc)));

    __shared__ float sb[256], sm2[256];
    sb[threadIdx.x] = l * m;
    sm2[threadIdx.x] = m;
    __syncthreads();
    for (int st = 128; st > 0; st >>= 1) {
        if (threadIdx.x < st) {
            sb[threadIdx.x] += sb[threadIdx.x + st];
            sm2[threadIdx.x] += sm2[threadIdx.x + st];
        }
        __syncthreads();
    }
    if (threadIdx.x == 0) partial[blockIdx.x] = make_float2(sb[0], sm2[0]);
}

__global__ void finalize_kernel(const float2* __restrict__ partial, int n,
                                float* __restrict__ out) {
    __shared__ float sa[32], sc[32];
    float a = 0.f, c = 0.f;
    if (threadIdx.x < n) { float2 p = partial[threadIdx.x]; a = p.x; c = p.y; }
    sa[threadIdx.x] = a; sc[threadIdx.x] = c;
    __syncthreads();
    for (int s = 16; s > 0; s >>= 1) {
        if (threadIdx.x < s) {
            sa[threadIdx.x] += sa[threadIdx.x + s];
            sc[threadIdx.x] += sc[threadIdx.x + s];
        }
        __syncthreads();
    }
    if (threadIdx.x == 0) out[0] = sa[0] / sc[0];
}

// ---------------- launch --------------------------------------------------------
extern "C" void kernel_launch(void* const* d_in, const int* in_sizes, int n_in,
                              void* d_out, int out_size) {
    const int*   x_data = (const int*)d_in[0];
    const int*   q_t    = (const int*)d_in[1];
    const float* target = (const float*)d_in[2];
    const float* rep    = (const float*)d_in[3];
    const float* past   = (const float*)d_in[4];
    const float* seq    = (const float*)d_in[5];
    const float* embed  = (const float*)d_in[6];
    const float* W_ih0  = (const float*)d_in[7];
    const float* W_hh0  = (const float*)d_in[8];
    const float* b_ih0  = (const float*)d_in[9];
    const float* b_hh0  = (const float*)d_in[10];
    const float* W_ih1  = (const float*)d_in[11];
    const float* W_hh1  = (const float*)d_in[12];
    const float* b_ih1  = (const float*)d_in[13];
    const float* b_hh1  = (const float*)d_in[14];
    const float* W_pred = (const float*)d_in[15];
    const float* b_pred = (const float*)d_in[16];
    const float* Cm     = (const float*)d_in[17];
    const float* init_h = (const float*)d_in[18];
    const float* init_c = (const float*)d_in[19];
    float* out = (float*)d_out;

    float *p_inpT, *p_X, *p_h1T, *p_WT, *p_h0A, *p_h0B, *p_h1A, *p_h1B;
    float *p_c0, *p_c1;
    float2* p_part;
    cudaGetSymbolAddress((void**)&p_inpT, g_inpT);
    cudaGetSymbolAddress((void**)&p_X,    g_X);
    cudaGetSymbolAddress((void**)&p_h1T,  g_hall1T);
    cudaGetSymbolAddress((void**)&p_WT,   g_WT);
    cudaGetSymbolAddress((void**)&p_h0A,  g_h0A);
    cudaGetSymbolAddress((void**)&p_h0B,  g_h0B);
    cudaGetSymbolAddress((void**)&p_h1A,  g_h1A);
    cudaGetSymbolAddress((void**)&p_h1B,  g_h1B);
    cudaGetSymbolAddress((void**)&p_c0,   g_cst0);
    cudaGetSymbolAddress((void**)&p_c1,   g_cst1);
    cudaGetSymbolAddress((void**)&p_part, g_partial);

    cudaFuncSetAttribute(gemm_tt_bias,
                         cudaFuncAttributeMaxDynamicSharedMemorySize, GSMEM);
    cudaFuncSetAttribute(fused_lstm_kernel,
                         cudaFuncAttributeMaxDynamicSharedMemorySize, FSMEM);

    // 1) build LSTM-0 input rows (k-major)
    build_inp_kernel<<<(M_ * IN0 + 255) / 256, 256>>>(x_data, embed, Cm, rep, seq,
                                                      past, p_inpT);
    // 2) X0 = inp @ W_ih0^T + b_ih0 + b_hh0
    transpose_kernel<<<dim3((IN0 + 31) / 32, G4 / 32), dim3(32, 8)>>>(W_ih0, p_WT,
                                                                      G4, IN0);
    gemm_tt_bias<<<dim3(G4 / 128, M_ / 128), 256, GSMEM>>>(p_inpT, p_WT, b_ih0,
                                                           b_hh0, p_X, M_, G4, IN0);
    // 3) init both layers' states
    init_state_kernel<<<(H_ * B_ + 255) / 256, 256>>>(init_h, init_c, p_h0A, p_c0,
                                                      p_h1A, p_c1);
    // 4) fused pipelined 2-layer scan (201 steps)
    fused_lstm_kernel<<<NCTA, 256, FSMEM>>>(p_X, W_hh0, W_ih1, W_hh1, b_ih1,
                                            b_hh1, p_h0A, p_h0B, p_h1A, p_h1B,
                                            p_c0, p_c1, p_h1T);
    // 5) gathered prediction head + BCE partials
    pred_kernel<<<M_ / 256, 256>>>(p_h1T, W_pred, b_pred, q_t, target, Cm, rep,
                                   seq, past, out, p_part);
    // 6) loss
    finalize_kernel<<<1, 32>>>(p_part, M_ / 256, out);
}

// round 14
// speedup vs baseline: 1.8368x; 1.0196x over previous
#include <cuda_runtime.h>
#include <math.h>

// R13 = R12 + parallel two-warpgroup epilogue (L0 on warps 0-3, L1 on warps
// 4-7 concurrently) + faster barrier wake (nanosleep 16).

#define B_   32
#define S_   200
#define H_   512
#define G4   2048
#define ED_  256
#define NF_  19
#define IN0  275
#define M_   6400
#define PD_  531
#define NCTA 128
#define TW   132                      // smem tile row stride (floats)

// ---------------- scratch (static device memory; no allocation) ----------------
__device__ float g_inpT[IN0 * M_];     // LSTM-0 input, k-major [IN0][M]
__device__ float g_X[M_ * G4];         // X0 = inp@Wih0^T + biases (row-major)
__device__ float g_hall1T[H_ * M_];    // layer-1 hidden, k-major [H][M]
__device__ float g_WT[512 * G4];       // transposed W_ih0
__device__ float g_h0A[H_ * B_];       // h0 ping ([H][B])
__device__ float g_h0B[H_ * B_];       // h0 pong
__device__ float g_h1A[H_ * B_];       // h1 ping
__device__ float g_h1B[H_ * B_];       // h1 pong
__device__ float g_cst0[H_ * B_];      // c0 init
__device__ float g_cst1[H_ * B_];      // c1 init
__device__ float2 g_partial[32];
__device__ unsigned int g_bar_count = 0;
__device__ volatile unsigned int g_bar_gen = 0;

// ---------------- packed fp32x2 helpers (Blackwell) ----------------------------
__device__ __forceinline__ unsigned long long pk2(float lo, float hi) {
    unsigned long long r;
    asm("mov.b64 %0,{%1,%2};" : "=l"(r) : "f"(lo), "f"(hi));
    return r;
}
__device__ __forceinline__ void ffma2(unsigned long long& d,
                                      unsigned long long a, unsigned long long b) {
    asm("fma.rn.f32x2 %0,%1,%2,%0;" : "+l"(d) : "l"(a), "l"(b));
}
__device__ __forceinline__ float2 up2(unsigned long long v) {
    float2 f;
    asm("mov.b64 {%0,%1},%2;" : "=f"(f.x), "=f"(f.y) : "l"(v));
    return f;
}
__device__ __forceinline__ void cp16(void* sdst, const void* gsrc) {
    unsigned s = (unsigned)__cvta_generic_to_shared(sdst);
    asm volatile("cp.async.cg.shared.global [%0],[%1],16;" :: "r"(s), "l"(gsrc));
}

// ---------------- grid-wide barrier (atomic + generation; known-good) -----------
__device__ __forceinline__ void grid_barrier(int nblocks) {
    __syncthreads();
    if (threadIdx.x == 0) {
        unsigned int gen = g_bar_gen;
        __threadfence();
        if (atomicAdd(&g_bar_count, 1u) == (unsigned)(nblocks - 1)) {
            g_bar_count = 0;
            __threadfence();
            g_bar_gen = gen + 1;
        } else {
            while (g_bar_gen == gen) { __nanosleep(16); }
        }
        __threadfence();
    }
    __syncthreads();
}

// ---------------- build LSTM-0 input (k-major transposed) -----------------------
__global__ void build_inp_kernel(const int* __restrict__ xd,
                                 const float* __restrict__ emb,
                                 const float* __restrict__ Cm,
                                 const float* __restrict__ rep,
                                 const float* __restrict__ seq,
                                 const float* __restrict__ past,
                                 float* __restrict__ inpT) {
    int idx = blockIdx.x * 256 + threadIdx.x;
    if (idx >= M_ * IN0) return;
    int d = idx / M_, col = idx - d * M_;
    int t = col >> 5, b = col & 31;
    float v;
    if (d < ED_) {
        int x = xd[b * S_ + t];
        v = emb[(size_t)x * ED_ + d];
    } else {
        int f = d - ED_;
        float cv;
        if (f < 7)       cv = rep[(b * (S_ + 1) + t) * 7 + f];
        else if (f < 13) cv = seq[(b * (S_ + 1) + t) * 6 + (f - 7)];
        else             cv = past[(b * (S_ + 1) + t) * 6 + (f - 13)];
        v = Cm[(b * S_ + t) * NF_ + f] * cv;
    }
    inpT[idx] = v;
}

// ---------------- generic tiled transpose: out[C][R] = in[R][C]^T ---------------
__global__ void transpose_kernel(const float* __restrict__ in,
                                 float* __restrict__ out, int R, int C) {
    __shared__ float tile[32][33];
    int c0 = blockIdx.x * 32, r0 = blockIdx.y * 32;
    int x = c0 + threadIdx.x;
#pragma unroll
    for (int j = 0; j < 32; j += 8) {
        int y = r0 + threadIdx.y + j;
        if (y < R && x < C) tile[threadIdx.y + j][threadIdx.x] = in[(size_t)y * C + x];
    }
    __syncthreads();
    int x2 = r0 + threadIdx.x;
#pragma unroll
    for (int j = 0; j < 32; j += 8) {
        int y2 = c0 + threadIdx.y + j;
        if (y2 < C && x2 < R) out[(size_t)y2 * R + x2] = tile[threadIdx.x][threadIdx.y + j];
    }
}

// ---------------- init both layers' states into [H][B] --------------------------
__global__ void init_state_kernel(const float* __restrict__ ih,
                                  const float* __restrict__ ic,
                                  float* __restrict__ h0A, float* __restrict__ cst0,
                                  float* __restrict__ h1A, float* __restrict__ cst1) {
    int idx = blockIdx.x * 256 + threadIdx.x;
    if (idx >= H_ * B_) return;
    int j = idx >> 5, b = idx & 31;
    h0A[j * B_ + b]  = ih[b * H_ + j];
    cst0[j * B_ + b] = ic[b * H_ + j];
    h1A[j * B_ + b]  = ih[B_ * H_ + b * H_ + j];
    cst1[j * B_ + b] = ic[B_ * H_ + b * H_ + j];
}

// ---------------- GEMM (k-major inputs): C[M][N] = AT^T * BT + bias1 + bias2 ----
__device__ __forceinline__ void gemm_load_stage(
    float* Abuf, float* Bbuf, const float* AT, const float* BT,
    int s, int m0, int n0, int M, int N, int K, int tid) {
    int off = (s % 3) * 32 * TW;
    int kk = s * 32;
#pragma unroll
    for (int i = 0; i < 4; i++) {
        int task = tid + i * 256;
        int row = task >> 5, c = task & 31;
        float* ad = &Abuf[off + row * TW + c * 4];
        float* bd = &Bbuf[off + row * TW + c * 4];
        if (kk + row < K) {
            cp16(ad, AT + (size_t)(kk + row) * M + m0 + c * 4);
            cp16(bd, BT + (size_t)(kk + row) * N + n0 + c * 4);
        } else {
            *(float4*)ad = make_float4(0.f, 0.f, 0.f, 0.f);
            *(float4*)bd = make_float4(0.f, 0.f, 0.f, 0.f);
        }
    }
    asm volatile("cp.async.commit_group;" ::);
}

__global__ void __launch_bounds__(256) gemm_tt_bias(
    const float* __restrict__ AT, const float* __restrict__ BT,
    const float* __restrict__ bias1, const float* __restrict__ bias2,
    float* __restrict__ Cmat, int M, int N, int K) {
    extern __shared__ float sm[];
    float* Abuf = sm;
    float* Bbuf = sm + 3 * 32 * TW;
    int m0 = blockIdx.y * 128, n0 = blockIdx.x * 128;
    int tid = threadIdx.x;
    int ty = tid >> 4, tx = tid & 15;
    int nk = (K + 31) / 32;

    unsigned long long acc[8][4];
#pragma unroll
    for (int i = 0; i < 8; i++)
#pragma unroll
        for (int j = 0; j < 4; j++) acc[i][j] = 0ull;

    gemm_load_stage(Abuf, Bbuf, AT, BT, 0, m0, n0, M, N, K, tid);
    if (nk > 1) gemm_load_stage(Abuf, Bbuf, AT, BT, 1, m0, n0, M, N, K, tid);

    for (int s = 0; s < nk; s++) {
        if (s + 2 < nk) {
            gemm_load_stage(Abuf, Bbuf, AT, BT, s + 2, m0, n0, M, N, K, tid);
            asm volatile("cp.async.wait_group 2;" ::);
        } else if (s + 1 < nk) {
            asm volatile("cp.async.wait_group 1;" ::);
        } else {
            asm volatile("cp.async.wait_group 0;" ::);
        }
        __syncthreads();
        const float* As = Abuf + (s % 3) * 32 * TW;
        const float* Bs = Bbuf + (s % 3) * 32 * TW;
#pragma unroll 8
        for (int k = 0; k < 32; k++) {
            float4 a0 = *(const float4*)&As[k * TW + ty * 8];
            float4 a1 = *(const float4*)&As[k * TW + ty * 8 + 4];
            ulonglong2 b0 = *(const ulonglong2*)&Bs[k * TW + tx * 8];
            ulonglong2 b1 = *(const ulonglong2*)&Bs[k * TW + tx * 8 + 4];
            unsigned long long aa[8];
            aa[0] = pk2(a0.x, a0.x); aa[1] = pk2(a0.y, a0.y);
            aa[2] = pk2(a0.z, a0.z); aa[3] = pk2(a0.w, a0.w);
            aa[4] = pk2(a1.x, a1.x); aa[5] = pk2(a1.y, a1.y);
            aa[6] = pk2(a1.z, a1.z); aa[7] = pk2(a1.w, a1.w);
#pragma unroll
            for (int i = 0; i < 8; i++) {
                ffma2(acc[i][0], aa[i], b0.x);
                ffma2(acc[i][1], aa[i], b0.y);
                ffma2(acc[i][2], aa[i], b1.x);
                ffma2(acc[i][3], aa[i], b1.y);
            }
        }
        __syncthreads();
    }
#pragma unroll
    for (int i = 0; i < 8; i++) {
        int m = m0 + ty * 8 + i;
#pragma unroll
        for (int j = 0; j < 4; j++) {
            int n = n0 + tx * 8 + j * 2;
            float2 v = up2(acc[i][j]);
            Cmat[(size_t)m * N + n]     = v.x + bias1[n]     + bias2[n];
            Cmat[(size_t)m * N + n + 1] = v.y + bias1[n + 1] + bias2[n + 1];
        }
    }
}
#define GSMEM (6 * 32 * TW * (int)sizeof(float))

// ---------------- fused 2-layer pipelined LSTM scan ------------------------------
// 128 CTAs x 256 threads. CTA owns units jb..jb+3 of BOTH layers.
// Step t: L0 computes h0_t (t<S); L1 computes h1_{t-1} (t>=1) using h0_{t-1}.
// Single h0 pass feeds BOTH W_hh0 (->a0) and W_ih1 (->a1).
// Epilogue split: warps 0-3 finish L0, warps 4-7 finish L1 CONCURRENTLY.
__global__ void __launch_bounds__(256, 1) fused_lstm_kernel(
    const float* __restrict__ X0,    // [S*B][4H], row = t*B+b (biases folded)
    const float* __restrict__ Whh0,  // [4H][H]
    const float* __restrict__ Wih1,  // [4H][H]
    const float* __restrict__ Whh1,  // [4H][H]
    const float* __restrict__ bih1,  // [4H]
    const float* __restrict__ bhh1,  // [4H]
    float* __restrict__ h0A, float* __restrict__ h0B,
    float* __restrict__ h1A, float* __restrict__ h1B,
    const float* __restrict__ cst0, const float* __restrict__ cst1,
    float* __restrict__ hall1T)      // [H][S*B]
{
    extern __shared__ float smem[];
    float* W0  = smem;                // [16][512] 32 KB  (W_hh0 rows)
    float* Wi  = smem + 8192;         // [16][512] 32 KB  (W_ih1 rows)
    float* Wh  = smem + 16384;        // [16][512] 32 KB  (W_hh1 rows)
    float* ps0 = smem + 24576;        // [8][16][32] 16 KB
    float* ps1 = smem + 28672;        // [8][16][32] 16 KB

    int tid = threadIdx.x;
    int jb = blockIdx.x * 4;
    int warp = tid >> 5, lane = tid & 31;

    for (int idx = tid; idx < 16 * 512; idx += 256) {
        int r = idx >> 9, k = idx & 511;
        int gr = (r >> 2) * H_ + jb + (r & 3);
        W0[idx] = Whh0[(size_t)gr * H_ + k];
        Wi[idx] = Wih1[(size_t)gr * H_ + k];
        Wh[idx] = Whh1[(size_t)gr * H_ + k];
    }
    // epilogue mapping: lower WG (tid<128) owns L0 unit u=warp; upper WG
    // (tid>=128) owns L1 unit u1=warp-4.
    int u = warp, b = lane;
    int u1 = warp - 4;
    float cc0 = 0.f, cc1 = 0.f;
    float b1i = 0.f, b1f = 0.f, b1g = 0.f, b1o = 0.f;
    if (tid < 128) {
        cc0 = cst0[(jb + u) * B_ + b];
    } else {
        cc1 = cst1[(jb + u1) * B_ + b];
        int gr = jb + u1;
        b1i = bih1[gr]          + bhh1[gr];
        b1f = bih1[H_ + gr]     + bhh1[H_ + gr];
        b1g = bih1[2 * H_ + gr] + bhh1[2 * H_ + gr];
        b1o = bih1[3 * H_ + gr] + bhh1[3 * H_ + gr];
    }
    __syncthreads();

    const int k0 = warp * 64;
    for (int t = 0; t <= S_; t++) {
        const bool doL0 = (t < S_);
        const bool doL1 = (t >= 1);
        const float* h0cur = (t & 1) ? h0B : h0A;
        float* h0nxt       = (t & 1) ? h0A : h0B;
        const float* h1cur = ((t - 1) & 1) ? h1B : h1A;
        float* h1nxt       = ((t - 1) & 1) ? h1A : h1B;

        // X0 prefetch for layer-0 epilogue (lower WG)
        float xi = 0.f, xf = 0.f, xg = 0.f, xo = 0.f;
        if (doL0 && tid < 128) {
            const float* xrow = X0 + (size_t)(t * B_ + b) * G4 + jb + u;
            xi = xrow[0]; xf = xrow[512]; xg = xrow[1024]; xo = xrow[1536];
        }

        unsigned long long a0[16], a1[16];
#pragma unroll
        for (int r = 0; r < 16; r++) { a0[r] = 0ull; a1[r] = 0ull; }

        // ---- merged h0 pass: a0 += W0@h0, a1 += Wi@h0 (same hv stream) ----
        {
            const float* hp0 = h0cur + k0 * B_ + lane;
#pragma unroll
            for (int kb = 0; kb < 8; kb++) {
                float h0 = __ldcg(hp0 + (kb * 8 + 0) * B_);
                float h1 = __ldcg(hp0 + (kb * 8 + 1) * B_);
                float h2 = __ldcg(hp0 + (kb * 8 + 2) * B_);
                float h3 = __ldcg(hp0 + (kb * 8 + 3) * B_);
                float h4 = __ldcg(hp0 + (kb * 8 + 4) * B_);
                float h5 = __ldcg(hp0 + (kb * 8 + 5) * B_);
                float h6 = __ldcg(hp0 + (kb * 8 + 6) * B_);
                float h7 = __ldcg(hp0 + (kb * 8 + 7) * B_);
                unsigned long long hv0 = pk2(h0, h1), hv1 = pk2(h2, h3);
                unsigned long long hv2 = pk2(h4, h5), hv3 = pk2(h6, h7);
                const float* wb0 = W0 + k0 + kb * 8;
                const float* wbi = Wi + k0 + kb * 8;
#pragma unroll
                for (int r = 0; r < 16; r++) {
                    ulonglong2 w0 = *(const ulonglong2*)(wb0 + r * 512);
                    ulonglong2 w1 = *(const ulonglong2*)(wb0 + r * 512 + 4);
                    ffma2(a0[r], hv0, w0.x);
                    ffma2(a0[r], hv1, w0.y);
                    ffma2(a0[r], hv2, w1.x);
                    ffma2(a0[r], hv3, w1.y);
                    ulonglong2 v0 = *(const ulonglong2*)(wbi + r * 512);
                    ulonglong2 v1 = *(const ulonglong2*)(wbi + r * 512 + 4);
                    ffma2(a1[r], hv0, v0.x);
                    ffma2(a1[r], hv1, v0.y);
                    ffma2(a1[r], hv2, v1.x);
                    ffma2(a1[r], hv3, v1.y);
                }
            }
        }
        // ---- h1 pass: a1 += Wh@h1 ----
        if (doL1) {
            const float* hp1 = h1cur + k0 * B_ + lane;
#pragma unroll
            for (int kb = 0; kb < 8; kb++) {
                float h0 = __ldcg(hp1 + (kb * 8 + 0) * B_);
                float h1 = __ldcg(hp1 + (kb * 8 + 1) * B_);
                float h2 = __ldcg(hp1 + (kb * 8 + 2) * B_);
                float h3 = __ldcg(hp1 + (kb * 8 + 3) * B_);
                float h4 = __ldcg(hp1 + (kb * 8 + 4) * B_);
                float h5 = __ldcg(hp1 + (kb * 8 + 5) * B_);
                float h6 = __ldcg(hp1 + (kb * 8 + 6) * B_);
                float h7 = __ldcg(hp1 + (kb * 8 + 7) * B_);
                unsigned long long hv0 = pk2(h0, h1), hv1 = pk2(h2, h3);
                unsigned long long hv2 = pk2(h4, h5), hv3 = pk2(h6, h7);
                const float* wb = Wh + k0 + kb * 8;
#pragma unroll
                for (int r = 0; r < 16; r++) {
                    ulonglong2 w0 = *(const ulonglong2*)(wb + r * 512);
                    ulonglong2 w1 = *(const ulonglong2*)(wb + r * 512 + 4);
                    ffma2(a1[r], hv0, w0.x);
                    ffma2(a1[r], hv1, w0.y);
                    ffma2(a1[r], hv2, w1.x);
                    ffma2(a1[r], hv3, w1.y);
                }
            }
        }
#pragma unroll
        for (int r = 0; r < 16; r++) {
            float2 p0 = up2(a0[r]);
            ps0[(warp * 16 + r) * 32 + lane] = p0.x + p0.y;
            float2 p1 = up2(a1[r]);
            ps1[(warp * 16 + r) * 32 + lane] = p1.x + p1.y;
        }
        __syncthreads();

        // ---- parallel epilogue: lower WG -> L0, upper WG -> L1 ----
        if (tid < 128) {
            if (doL0) {
                float s_i = xi, s_f = xf, s_g = xg, s_o = xo;
#pragma unroll
                for (int w = 0; w < 8; w++) {
                    s_i += ps0[(w * 16 + 0  + u) * 32 + b];
                    s_f += ps0[(w * 16 + 4  + u) * 32 + b];
                    s_g += ps0[(w * 16 + 8  + u) * 32 + b];
                    s_o += ps0[(w * 16 + 12 + u) * 32 + b];
                }
                float ig = 1.f / (1.f + expf(-s_i));
                float fg = 1.f / (1.f + expf(-s_f));
                float og = 1.f / (1.f + expf(-s_o));
                cc0 = fg * cc0 + ig * tanhf(s_g);
                float hv = og * tanhf(cc0);
                __stcg(&h0nxt[(jb + u) * B_ + b], hv);
            }
        } else {
            if (doL1) {
                float s_i = b1i, s_f = b1f, s_g = b1g, s_o = b1o;
#pragma unroll
                for (int w = 0; w < 8; w++) {
                    s_i += ps1[(w * 16 + 0  + u1) * 32 + b];
                    s_f += ps1[(w * 16 + 4  + u1) * 32 + b];
                    s_g += ps1[(w * 16 + 8  + u1) * 32 + b];
                    s_o += ps1[(w * 16 + 12 + u1) * 32 + b];
                }
                float ig = 1.f / (1.f + expf(-s_i));
                float fg = 1.f / (1.f + expf(-s_f));
                float og = 1.f / (1.f + expf(-s_o));
                cc1 = fg * cc1 + ig * tanhf(s_g);
                float hv = og * tanhf(cc1);
                __stcg(&h1nxt[(jb + u1) * B_ + b], hv);
                hall1T[(size_t)(jb + u1) * M_ + (t - 1) * B_ + b] = hv;
            }
        }
        if (t < S_) grid_barrier(NCTA);   // last iteration needs no barrier
    }
}
#define FSMEM ((3 * 16 * 512 + 2 * 8 * 16 * 32) * (int)sizeof(float))

// ---------------- gathered prediction + BCE partials ----------------------------
__global__ void pred_kernel(const float* __restrict__ hallT,
                            const float* __restrict__ Wp,
                            const float* __restrict__ bp,
                            const int* __restrict__ qt,
                            const float* __restrict__ target,
                            const float* __restrict__ Cm,
                            const float* __restrict__ rep,
                            const float* __restrict__ seq,
                            const float* __restrict__ past,
                            float* __restrict__ out,
                            float2* __restrict__ partial) {
    int col = blockIdx.x * 256 + threadIdx.x;     // t*B+b ordering
    int b = col & 31, s = col >> 5;
    int r = b * S_ + s;
    int q = qt[r];
    const float* wrow = Wp + (size_t)q * PD_;
    const float* hc = hallT + col;
    float acc = bp[q];
#pragma unroll 8
    for (int d = 0; d < H_; d++) acc = fmaf(hc[(size_t)d * M_], wrow[d], acc);
#pragma unroll
    for (int f = 0; f < NF_; f++) {
        float cv;
        if (f < 7)       cv = rep[(b * (S_ + 1) + s + 1) * 7 + f];
        else if (f < 13) cv = seq[(b * (S_ + 1) + s + 1) * 6 + (f - 7)];
        else             cv = past[(b * (S_ + 1) + s + 1) * 6 + (f - 13)];
        float pi = Cm[(b * S_ + s) * NF_ + f] * cv;
        acc = fmaf(pi, wrow[H_ + f], acc);
    }
    float m = (q > 0) ? 1.f : 0.f;
    float tt = target[r];
    float sg = 1.f / (1.f + expf(-acc));
    out[1 + r] = sg * m;
    out[1 + M_ + r] = tt * m;
    float l = fmaxf(acc, 0.f) - acc * tt + log1pf(expf(-fabsf(acc)));

    __shared__ float sb[256], sm2[256];
    sb[threadIdx.x] = l * m;
    sm2[threadIdx.x] = m;
    __syncthreads();
    for (int st = 128; st > 0; st >>= 1) {
        if (threadIdx.x < st) {
            sb[threadIdx.x] += sb[threadIdx.x + st];
            sm2[threadIdx.x] += sm2[threadIdx.x + st];
        }
        __syncthreads();
    }
    if (threadIdx.x == 0) partial[blockIdx.x] = make_float2(sb[0], sm2[0]);
}

__global__ void finalize_kernel(const float2* __restrict__ partial, int n,
                                float* __restrict__ out) {
    __shared__ float sa[32], sc[32];
    float a = 0.f, c = 0.f;
    if (threadIdx.x < n) { float2 p = partial[threadIdx.x]; a = p.x; c = p.y; }
    sa[threadIdx.x] = a; sc[threadIdx.x] = c;
    __syncthreads();
    for (int s = 16; s > 0; s >>= 1) {
        if (threadIdx.x < s) {
            sa[threadIdx.x] += sa[threadIdx.x + s];
            sc[threadIdx.x] += sc[threadIdx.x + s];
        }
        __syncthreads();
    }
    if (threadIdx.x == 0) out[0] = sa[0] / sc[0];
}

// ---------------- launch --------------------------------------------------------
extern "C" void kernel_launch(void* const* d_in, const int* in_sizes, int n_in,
                              void* d_out, int out_size) {
    const int*   x_data = (const int*)d_in[0];
    const int*   q_t    = (const int*)d_in[1];
    const float* target = (const float*)d_in[2];
    const float* rep    = (const float*)d_in[3];
    const float* past   = (const float*)d_in[4];
    const float* seq    = (const float*)d_in[5];
    const float* embed  = (const float*)d_in[6];
    const float* W_ih0  = (const float*)d_in[7];
    const float* W_hh0  = (const float*)d_in[8];
    const float* b_ih0  = (const float*)d_in[9];
    const float* b_hh0  = (const float*)d_in[10];
    const float* W_ih1  = (const float*)d_in[11];
    const float* W_hh1  = (const float*)d_in[12];
    const float* b_ih1  = (const float*)d_in[13];
    const float* b_hh1  = (const float*)d_in[14];
    const float* W_pred = (const float*)d_in[15];
    const float* b_pred = (const float*)d_in[16];
    const float* Cm     = (const float*)d_in[17];
    const float* init_h = (const float*)d_in[18];
    const float* init_c = (const float*)d_in[19];
    float* out = (float*)d_out;

    float *p_inpT, *p_X, *p_h1T, *p_WT, *p_h0A, *p_h0B, *p_h1A, *p_h1B;
    float *p_c0, *p_c1;
    float2* p_part;
    cudaGetSymbolAddress((void**)&p_inpT, g_inpT);
    cudaGetSymbolAddress((void**)&p_X,    g_X);
    cudaGetSymbolAddress((void**)&p_h1T,  g_hall1T);
    cudaGetSymbolAddress((void**)&p_WT,   g_WT);
    cudaGetSymbolAddress((void**)&p_h0A,  g_h0A);
    cudaGetSymbolAddress((void**)&p_h0B,  g_h0B);
    cudaGetSymbolAddress((void**)&p_h1A,  g_h1A);
    cudaGetSymbolAddress((void**)&p_h1B,  g_h1B);
    cudaGetSymbolAddress((void**)&p_c0,   g_cst0);
    cudaGetSymbolAddress((void**)&p_c1,   g_cst1);
    cudaGetSymbolAddress((void**)&p_part, g_partial);

    cudaFuncSetAttribute(gemm_tt_bias,
                         cudaFuncAttributeMaxDynamicSharedMemorySize, GSMEM);
    cudaFuncSetAttribute(fused_lstm_kernel,
                         cudaFuncAttributeMaxDynamicSharedMemorySize, FSMEM);

    // 1) build LSTM-0 input rows (k-major)
    build_inp_kernel<<<(M_ * IN0 + 255) / 256, 256>>>(x_data, embed, Cm, rep, seq,
                                                      past, p_inpT);
    // 2) X0 = inp @ W_ih0^T + b_ih0 + b_hh0
    transpose_kernel<<<dim3((IN0 + 31) / 32, G4 / 32), dim3(32, 8)>>>(W_ih0, p_WT,
                                                                      G4, IN0);
    gemm_tt_bias<<<dim3(G4 / 128, M_ / 128), 256, GSMEM>>>(p_inpT, p_WT, b_ih0,
                                                           b_hh0, p_X, M_, G4, IN0);
    // 3) init both layers' states
    init_state_kernel<<<(H_ * B_ + 255) / 256, 256>>>(init_h, init_c, p_h0A, p_c0,
                                                      p_h1A, p_c1);
    // 4) fused pipelined 2-layer scan (201 steps)
    fused_lstm_kernel<<<NCTA, 256, FSMEM>>>(p_X, W_hh0, W_ih1, W_hh1, b_ih1,
                                            b_hh1, p_h0A, p_h0B, p_h1A, p_h1B,
                                            p_c0, p_c1, p_h1T);
    // 5) gathered prediction head + BCE partials
    pred_kernel<<<M_ / 256, 256>>>(p_h1T, W_pred, b_pred, q_t, target, Cm, rep,
                                   seq, past, out, p_part);
    // 6) loss
    finalize_kernel<<<1, 32>>>(p_part, M_ / 256, out);
}